// round 1
// baseline (speedup 1.0000x reference)
#include <cuda_runtime.h>
#include <math.h>

#define BB  4
#define SS  2048
#define PP  32
#define DD  512
#define HH  8
#define LL  2
#define DF  2048
#define HD  64
#define MM  (BB*SS)   /* 8192 rows */

// ---------------- scratch (device globals; no allocations allowed) ----------
__device__ float g_h [MM*DD];
__device__ float g_q [MM*DD];
__device__ float g_k [MM*DD];
__device__ float g_v [MM*DD];
__device__ float g_o [MM*DD];
__device__ float g_t [MM*DD];
__device__ float g_ff[MM*DF];
__device__ float g_cos[SS*32];
__device__ float g_sin[SS*32];

// ---------------- RoPE tables ----------------------------------------------
// ref: inv[j]=10000^-(2j/64); ch[i]=cos(pos*inv[fidx]), fidx=(2i)%32
__global__ void rope_tables_kernel(float* __restrict__ ct, float* __restrict__ st) {
    int idx = blockIdx.x * blockDim.x + threadIdx.x;
    if (idx >= SS * 32) return;
    int pos = idx >> 5;
    int i   = idx & 31;
    int fidx = (2 * i) & 31;
    float ex  = (float)(2 * fidx) / 64.0f;
    float inv = 1.0f / powf(10000.0f, ex);
    float ang = (float)pos * inv;
    ct[idx] = cosf(ang);
    st[idx] = sinf(ang);
}

// in-place rotate pairs (x[2i], x[2i+1]) of each head slice
__global__ void rope_apply_kernel(float* __restrict__ q,
                                  const float* __restrict__ ct,
                                  const float* __restrict__ st) {
    int idx = blockIdx.x * blockDim.x + threadIdx.x;   // MM*HH*32 threads
    int i   = idx & 31;
    int rem = idx >> 5;
    int hh  = rem & (HH - 1);
    int row = rem >> 3;                 // b*SS + s
    int s   = row & (SS - 1);
    float c  = ct[s * 32 + i];
    float sn = st[s * 32 + i];
    float* p = q + (size_t)row * DD + hh * HD + 2 * i;
    float x1 = p[0], x2 = p[1];
    p[0] = x1 * c - x2 * sn;
    p[1] = x1 * sn + x2 * c;
}

// ---------------- SGEMM: C = A[MxK] @ B[KxN] + bias, optional exact GELU ----
// BM=BN=128, BK=8, 256 threads, 8x8 microtile. Requires M%128==0, N%128==0, K%8==0.
template <int GELU>
__global__ void __launch_bounds__(256)
sgemm_bias(const float* __restrict__ A, const float* __restrict__ B,
           const float* __restrict__ bias, float* __restrict__ C,
           int M, int N, int K) {
    __shared__ float As[8][128];
    __shared__ float Bs[8][128];
    int tid = threadIdx.x;
    int bx = blockIdx.x;     // N tile
    int by = blockIdx.y;     // M tile
    int tx = tid & 15;
    int ty = tid >> 4;

    float acc[8][8];
#pragma unroll
    for (int i = 0; i < 8; i++)
#pragma unroll
        for (int j = 0; j < 8; j++) acc[i][j] = 0.0f;

    int aRow = tid >> 1;            // 0..127
    int aCol = (tid & 1) * 4;       // 0 or 4
    int bRow = tid >> 5;            // 0..7
    int bCol = (tid & 31) * 4;      // 0..124

    const float* Ap = A + (size_t)(by * 128 + aRow) * K + aCol;
    const float* Bp = B + (size_t)bRow * N + bx * 128 + bCol;

    for (int k0 = 0; k0 < K; k0 += 8) {
        float4 a4 = *(const float4*)Ap;  Ap += 8;
        As[aCol + 0][aRow] = a4.x;
        As[aCol + 1][aRow] = a4.y;
        As[aCol + 2][aRow] = a4.z;
        As[aCol + 3][aRow] = a4.w;
        float4 b4 = *(const float4*)Bp;  Bp += (size_t)8 * N;
        *(float4*)&Bs[bRow][bCol] = b4;
        __syncthreads();
#pragma unroll
        for (int kk = 0; kk < 8; kk++) {
            float ra[8], rb[8];
#pragma unroll
            for (int i = 0; i < 8; i++) ra[i] = As[kk][ty * 8 + i];
#pragma unroll
            for (int j = 0; j < 8; j++) rb[j] = Bs[kk][tx * 8 + j];
#pragma unroll
            for (int i = 0; i < 8; i++)
#pragma unroll
                for (int j = 0; j < 8; j++) acc[i][j] += ra[i] * rb[j];
        }
        __syncthreads();
    }

#pragma unroll
    for (int i = 0; i < 8; i++) {
        int row = by * 128 + ty * 8 + i;
#pragma unroll
        for (int j = 0; j < 8; j++) {
            int col = bx * 128 + tx * 8 + j;
            float val = acc[i][j] + bias[col];
            if (GELU) val = 0.5f * val * (1.0f + erff(val * 0.70710678118654752f));
            C[(size_t)row * N + col] = val;
        }
    }
}

// ---------------- naive head GEMM: out[M x 32] = h @ Wh + bh ----------------
__global__ void head_gemm_kernel(const float* __restrict__ h,
                                 const float* __restrict__ Wh,
                                 const float* __restrict__ bh,
                                 float* __restrict__ out) {
    int idx = blockIdx.x * blockDim.x + threadIdx.x;   // MM*PP
    int n = idx & (PP - 1);
    int m = idx / PP;
    float acc = bh[n];
    const float* hp = h + (size_t)m * DD;
#pragma unroll 8
    for (int k = 0; k < DD; k++) acc += hp[k] * Wh[k * PP + n];
    out[idx] = acc;
}

// ---------------- residual add + LayerNorm (in-place into h) ----------------
__global__ void add_ln_kernel(float* __restrict__ h, const float* __restrict__ d,
                              const float* __restrict__ g, const float* __restrict__ b) {
    int row = blockIdx.x;
    int t   = threadIdx.x;        // 128 threads, 4 elems each
    float4 hv = *(float4*)(h + (size_t)row * DD + t * 4);
    float4 dv = *(const float4*)(d + (size_t)row * DD + t * 4);
    float v0 = hv.x + dv.x, v1 = hv.y + dv.y, v2 = hv.z + dv.z, v3 = hv.w + dv.w;
    float s  = v0 + v1 + v2 + v3;
    float s2 = v0 * v0 + v1 * v1 + v2 * v2 + v3 * v3;
#pragma unroll
    for (int off = 16; off; off >>= 1) {
        s  += __shfl_xor_sync(0xFFFFFFFF, s,  off);
        s2 += __shfl_xor_sync(0xFFFFFFFF, s2, off);
    }
    __shared__ float sh[8];
    int w = t >> 5, lane = t & 31;
    if (lane == 0) { sh[w] = s; sh[4 + w] = s2; }
    __syncthreads();
    s  = sh[0] + sh[1] + sh[2] + sh[3];
    s2 = sh[4] + sh[5] + sh[6] + sh[7];
    float mean = s * (1.0f / DD);
    float var  = s2 * (1.0f / DD) - mean * mean;
    float inv  = rsqrtf(var + 1e-5f);
    float4 gv = *(const float4*)(g + t * 4);
    float4 bv = *(const float4*)(b + t * 4);
    float4 o;
    o.x = (v0 - mean) * inv * gv.x + bv.x;
    o.y = (v1 - mean) * inv * gv.y + bv.y;
    o.z = (v2 - mean) * inv * gv.z + bv.z;
    o.w = (v3 - mean) * inv * gv.w + bv.w;
    *(float4*)(h + (size_t)row * DD + t * 4) = o;
}

// ---------------- attention: warp per query, 32-key shared tiles ------------
// scores = (q.k)*0.125 + (vid_q==vid_k ? u_same[h] : u_cross[h]) + (1-mask_k)*-1e9
__global__ void __launch_bounds__(256)
attn_kernel(const float* __restrict__ q, const float* __restrict__ k,
            const float* __restrict__ v, const int* __restrict__ vids,
            const float* __restrict__ mask,
            const float* __restrict__ u_same, const float* __restrict__ u_cross,
            float* __restrict__ o) {
    __shared__ float Ks[32][64];
    __shared__ float Vs[32][64];
    __shared__ int   svid[32];
    __shared__ float smask[32];

    int qbase = blockIdx.x * 8;           // 8 queries (8 warps) per block, same (b,h)
    int s0 = qbase & (SS - 1);
    int bh = qbase / SS;
    int hh = bh & (HH - 1);
    int b  = bh / HH;
    int warp = threadIdx.x >> 5;
    int lane = threadIdx.x & 31;
    int sq = s0 + warp;

    const float* qp = q + ((size_t)(b * SS + sq)) * DD + hh * HD;
    float2 qv = *(const float2*)(qp + 2 * lane);
    int   vid_q = vids[b * SS + sq];
    float us = u_same[hh], uc = u_cross[hh];

    float m = -1e30f, ssum = 0.0f;
    float2 oacc = make_float2(0.0f, 0.0f);

    for (int kt = 0; kt < SS; kt += 32) {
        int t = threadIdx.x;
        const float* kb = k + ((size_t)(b * SS + kt)) * DD + hh * HD;
        const float* vb = v + ((size_t)(b * SS + kt)) * DD + hh * HD;
        int row = t >> 3;
        int col = (t & 7) * 8;
        *(float4*)&Ks[row][col]     = *(const float4*)(kb + (size_t)row * DD + col);
        *(float4*)&Ks[row][col + 4] = *(const float4*)(kb + (size_t)row * DD + col + 4);
        *(float4*)&Vs[row][col]     = *(const float4*)(vb + (size_t)row * DD + col);
        *(float4*)&Vs[row][col + 4] = *(const float4*)(vb + (size_t)row * DD + col + 4);
        if (t < 32) {
            svid[t]  = vids[b * SS + kt + t];
            smask[t] = (1.0f - mask[b * SS + kt + t]) * -1e9f;
        }
        __syncthreads();

#pragma unroll 4
        for (int kk = 0; kk < 32; kk++) {
            float2 k2 = *(const float2*)&Ks[kk][2 * lane];
            float partial = qv.x * k2.x + qv.y * k2.y;
            partial += __shfl_xor_sync(0xFFFFFFFF, partial, 16);
            partial += __shfl_xor_sync(0xFFFFFFFF, partial, 8);
            partial += __shfl_xor_sync(0xFFFFFFFF, partial, 4);
            partial += __shfl_xor_sync(0xFFFFFFFF, partial, 2);
            partial += __shfl_xor_sync(0xFFFFFFFF, partial, 1);
            float sc = partial * 0.125f + (svid[kk] == vid_q ? us : uc) + smask[kk];
            float newm = fmaxf(m, sc);
            float corr = __expf(m - newm);
            float p    = __expf(sc - newm);
            ssum = ssum * corr + p;
            float2 v2 = *(const float2*)&Vs[kk][2 * lane];
            oacc.x = oacc.x * corr + p * v2.x;
            oacc.y = oacc.y * corr + p * v2.y;
            m = newm;
        }
        __syncthreads();
    }

    float invs = 1.0f / ssum;
    float* op = o + ((size_t)(b * SS + sq)) * DD + hh * HD + 2 * lane;
    op[0] = oacc.x * invs;
    op[1] = oacc.y * invs;
}

// ---------------- driver -----------------------------------------------------
extern "C" void kernel_launch(void* const* d_in, const int* in_sizes, int n_in,
                              void* d_out, int out_size) {
    const float* x      = (const float*)d_in[0];
    const int*   vids   = (const int*)  d_in[1];
    const float* mask   = (const float*)d_in[2];
    const float* W_pe   = (const float*)d_in[3];
    const float* b_pe   = (const float*)d_in[4];
    const float* Wq     = (const float*)d_in[5];
    const float* bq     = (const float*)d_in[6];
    const float* Wk     = (const float*)d_in[7];
    const float* bk     = (const float*)d_in[8];
    const float* Wv     = (const float*)d_in[9];
    const float* bv     = (const float*)d_in[10];
    const float* Wo     = (const float*)d_in[11];
    const float* bo     = (const float*)d_in[12];
    const float* u_same = (const float*)d_in[13];
    const float* u_cross= (const float*)d_in[14];
    const float* g1     = (const float*)d_in[15];
    const float* be1    = (const float*)d_in[16];
    const float* W1     = (const float*)d_in[17];
    const float* b1f    = (const float*)d_in[18];
    const float* W2     = (const float*)d_in[19];
    const float* b2f    = (const float*)d_in[20];
    const float* g2     = (const float*)d_in[21];
    const float* be2    = (const float*)d_in[22];
    const float* Wh     = (const float*)d_in[23];
    const float* bh     = (const float*)d_in[24];
    float* out = (float*)d_out;

    float *ph, *pq, *pk, *pv, *po, *pt, *pff, *pc, *ps;
    cudaGetSymbolAddress((void**)&ph,  g_h);
    cudaGetSymbolAddress((void**)&pq,  g_q);
    cudaGetSymbolAddress((void**)&pk,  g_k);
    cudaGetSymbolAddress((void**)&pv,  g_v);
    cudaGetSymbolAddress((void**)&po,  g_o);
    cudaGetSymbolAddress((void**)&pt,  g_t);
    cudaGetSymbolAddress((void**)&pff, g_ff);
    cudaGetSymbolAddress((void**)&pc,  g_cos);
    cudaGetSymbolAddress((void**)&ps,  g_sin);

    rope_tables_kernel<<<(SS * 32 + 255) / 256, 256>>>(pc, ps);

    // h = x @ W_pe + b_pe   (M=8192, N=512, K=32)
    sgemm_bias<0><<<dim3(DD / 128, MM / 128), 256>>>(x, W_pe, b_pe, ph, MM, DD, PP);

    for (int l = 0; l < LL; l++) {
        const float* Wql = Wq + (size_t)l * DD * DD;
        const float* Wkl = Wk + (size_t)l * DD * DD;
        const float* Wvl = Wv + (size_t)l * DD * DD;
        const float* Wol = Wo + (size_t)l * DD * DD;
        const float* W1l = W1 + (size_t)l * DD * DF;
        const float* W2l = W2 + (size_t)l * DF * DD;

        sgemm_bias<0><<<dim3(DD / 128, MM / 128), 256>>>(ph, Wql, bq + l * DD, pq, MM, DD, DD);
        sgemm_bias<0><<<dim3(DD / 128, MM / 128), 256>>>(ph, Wkl, bk + l * DD, pk, MM, DD, DD);
        sgemm_bias<0><<<dim3(DD / 128, MM / 128), 256>>>(ph, Wvl, bv + l * DD, pv, MM, DD, DD);

        rope_apply_kernel<<<(MM * HH * 32) / 256, 256>>>(pq, pc, ps);
        rope_apply_kernel<<<(MM * HH * 32) / 256, 256>>>(pk, pc, ps);

        attn_kernel<<<(BB * HH * SS) / 8, 256>>>(pq, pk, pv, vids, mask,
                                                 u_same + l * HH, u_cross + l * HH, po);

        sgemm_bias<0><<<dim3(DD / 128, MM / 128), 256>>>(po, Wol, bo + l * DD, pt, MM, DD, DD);
        add_ln_kernel<<<MM, 128>>>(ph, pt, g1 + l * DD, be1 + l * DD);

        sgemm_bias<1><<<dim3(DF / 128, MM / 128), 256>>>(ph, W1l, b1f + l * DF, pff, MM, DF, DD);
        sgemm_bias<0><<<dim3(DD / 128, MM / 128), 256>>>(pff, W2l, b2f + l * DD, pt, MM, DD, DF);
        add_ln_kernel<<<MM, 128>>>(ph, pt, g2 + l * DD, be2 + l * DD);
    }

    head_gemm_kernel<<<(MM * PP) / 256, 256>>>(ph, Wh, bh, out);
}

// round 2
// speedup vs baseline: 2.7248x; 2.7248x over previous
#include <cuda_runtime.h>
#include <math.h>

#define BB  4
#define SS  2048
#define PP  32
#define DD  512
#define HH  8
#define LL  2
#define DF  2048
#define HD  64
#define MM  (BB*SS)   /* 8192 rows */

// ---------------- scratch (device globals; no allocations allowed) ----------
__device__ float g_h [MM*DD];
__device__ float g_q [MM*DD];
__device__ float g_k [MM*DD];
__device__ float g_v [MM*DD];
__device__ float g_o [MM*DD];
__device__ float g_t [MM*DD];
__device__ float g_ff[MM*DF];
__device__ float g_cos[SS*32];
__device__ float g_sin[SS*32];

// ---------------- RoPE tables ----------------------------------------------
__global__ void rope_tables_kernel(float* __restrict__ ct, float* __restrict__ st) {
    int idx = blockIdx.x * blockDim.x + threadIdx.x;
    if (idx >= SS * 32) return;
    int pos = idx >> 5;
    int i   = idx & 31;
    int fidx = (2 * i) & 31;
    float ex  = (float)(2 * fidx) / 64.0f;
    float inv = 1.0f / powf(10000.0f, ex);
    float ang = (float)pos * inv;
    ct[idx] = cosf(ang);
    st[idx] = sinf(ang);
}

__global__ void rope_apply_kernel(float* __restrict__ q,
                                  const float* __restrict__ ct,
                                  const float* __restrict__ st) {
    int idx = blockIdx.x * blockDim.x + threadIdx.x;   // MM*HH*32 threads
    int i   = idx & 31;
    int rem = idx >> 5;
    int hh  = rem & (HH - 1);
    int row = rem >> 3;
    int s   = row & (SS - 1);
    float c  = ct[s * 32 + i];
    float sn = st[s * 32 + i];
    float* p = q + (size_t)row * DD + hh * HD + 2 * i;
    float x1 = p[0], x2 = p[1];
    p[0] = x1 * c - x2 * sn;
    p[1] = x1 * sn + x2 * c;
}

// ---------------- SGEMM: C = A[MxK] @ B[KxN] + bias, optional exact GELU ----
template <int GELU>
__global__ void __launch_bounds__(256)
sgemm_bias(const float* __restrict__ A, const float* __restrict__ B,
           const float* __restrict__ bias, float* __restrict__ C,
           int M, int N, int K) {
    __shared__ float As[8][128];
    __shared__ float Bs[8][128];
    int tid = threadIdx.x;
    int bx = blockIdx.x;
    int by = blockIdx.y;
    int tx = tid & 15;
    int ty = tid >> 4;

    float acc[8][8];
#pragma unroll
    for (int i = 0; i < 8; i++)
#pragma unroll
        for (int j = 0; j < 8; j++) acc[i][j] = 0.0f;

    int aRow = tid >> 1;
    int aCol = (tid & 1) * 4;
    int bRow = tid >> 5;
    int bCol = (tid & 31) * 4;

    const float* Ap = A + (size_t)(by * 128 + aRow) * K + aCol;
    const float* Bp = B + (size_t)bRow * N + bx * 128 + bCol;

    for (int k0 = 0; k0 < K; k0 += 8) {
        float4 a4 = *(const float4*)Ap;  Ap += 8;
        As[aCol + 0][aRow] = a4.x;
        As[aCol + 1][aRow] = a4.y;
        As[aCol + 2][aRow] = a4.z;
        As[aCol + 3][aRow] = a4.w;
        float4 b4 = *(const float4*)Bp;  Bp += (size_t)8 * N;
        *(float4*)&Bs[bRow][bCol] = b4;
        __syncthreads();
#pragma unroll
        for (int kk = 0; kk < 8; kk++) {
            float ra[8], rb[8];
#pragma unroll
            for (int i = 0; i < 8; i++) ra[i] = As[kk][ty * 8 + i];
#pragma unroll
            for (int j = 0; j < 8; j++) rb[j] = Bs[kk][tx * 8 + j];
#pragma unroll
            for (int i = 0; i < 8; i++)
#pragma unroll
                for (int j = 0; j < 8; j++) acc[i][j] += ra[i] * rb[j];
        }
        __syncthreads();
    }

#pragma unroll
    for (int i = 0; i < 8; i++) {
        int row = by * 128 + ty * 8 + i;
#pragma unroll
        for (int j = 0; j < 8; j++) {
            int col = bx * 128 + tx * 8 + j;
            float val = acc[i][j] + bias[col];
            if (GELU) val = 0.5f * val * (1.0f + erff(val * 0.70710678118654752f));
            C[(size_t)row * N + col] = val;
        }
    }
}

// ---------------- naive head GEMM: out[M x 32] = h @ Wh + bh ----------------
__global__ void head_gemm_kernel(const float* __restrict__ h,
                                 const float* __restrict__ Wh,
                                 const float* __restrict__ bh,
                                 float* __restrict__ out) {
    int idx = blockIdx.x * blockDim.x + threadIdx.x;
    int n = idx & (PP - 1);
    int m = idx / PP;
    float acc = bh[n];
    const float* hp = h + (size_t)m * DD;
#pragma unroll 8
    for (int k = 0; k < DD; k++) acc += hp[k] * Wh[k * PP + n];
    out[idx] = acc;
}

// ---------------- residual add + LayerNorm (in-place into h) ----------------
__global__ void add_ln_kernel(float* __restrict__ h, const float* __restrict__ d,
                              const float* __restrict__ g, const float* __restrict__ b) {
    int row = blockIdx.x;
    int t   = threadIdx.x;
    float4 hv = *(float4*)(h + (size_t)row * DD + t * 4);
    float4 dv = *(const float4*)(d + (size_t)row * DD + t * 4);
    float v0 = hv.x + dv.x, v1 = hv.y + dv.y, v2 = hv.z + dv.z, v3 = hv.w + dv.w;
    float s  = v0 + v1 + v2 + v3;
    float s2 = v0 * v0 + v1 * v1 + v2 * v2 + v3 * v3;
#pragma unroll
    for (int off = 16; off; off >>= 1) {
        s  += __shfl_xor_sync(0xFFFFFFFF, s,  off);
        s2 += __shfl_xor_sync(0xFFFFFFFF, s2, off);
    }
    __shared__ float sh[8];
    int w = t >> 5, lane = t & 31;
    if (lane == 0) { sh[w] = s; sh[4 + w] = s2; }
    __syncthreads();
    s  = sh[0] + sh[1] + sh[2] + sh[3];
    s2 = sh[4] + sh[5] + sh[6] + sh[7];
    float mean = s * (1.0f / DD);
    float var  = s2 * (1.0f / DD) - mean * mean;
    float inv  = rsqrtf(var + 1e-5f);
    float4 gv = *(const float4*)(g + t * 4);
    float4 bv = *(const float4*)(b + t * 4);
    float4 o;
    o.x = (v0 - mean) * inv * gv.x + bv.x;
    o.y = (v1 - mean) * inv * gv.y + bv.y;
    o.z = (v2 - mean) * inv * gv.z + bv.z;
    o.w = (v3 - mean) * inv * gv.w + bv.w;
    *(float4*)(h + (size_t)row * DD + t * 4) = o;
}

// ---------------- flash attention, tiled GEMM formulation -------------------
// Block = 64 queries of one (b,h). 256 threads = 16x16, 4x4 microtile.
// Per 64-key tile: S = Q@K^T (SIMT GEMM) -> online softmax -> O += P@V.
// Dynamic smem layout (floats):
//   Qs [64][64]  (Qs[d][q], transposed)           ofs 0
//   Ks [64][64]  (Ks[d][k], transposed)           ofs 4096
//   Vs [64][64]  (Vs[k][d], natural)              ofs 8192
//   Ps [64][68]  (Ps[k][q], padded for banks)     ofs 12288
//   svid[64] (int), smaskv[64]                    ofs 16640, 16704
#define ATTN_SMEM_FLOATS (16768)

__global__ void __launch_bounds__(256)
attn2_kernel(const float* __restrict__ q, const float* __restrict__ k,
             const float* __restrict__ v, const int* __restrict__ vids,
             const float* __restrict__ mask,
             const float* __restrict__ u_same, const float* __restrict__ u_cross,
             float* __restrict__ o) {
    extern __shared__ float smem[];
    float* Qs = smem;                 // [64][64]
    float* Ks = smem + 4096;          // [64][64]
    float* Vs = smem + 8192;          // [64][64]
    float* Ps = smem + 12288;         // [64][68]
    int*   svid   = (int*)(smem + 16640);
    float* smaskv = smem + 16704;

    int tid = threadIdx.x;
    int tx = tid & 15;                // key / dim microtile col
    int ty = tid >> 4;                // query microtile row

    int qt = blockIdx.x & (SS / 64 - 1);
    int bh = blockIdx.x / (SS / 64);
    int hh = bh & (HH - 1);
    int b  = bh / HH;
    int q0 = qt * 64;                 // first query of this block

    const float us = u_same[hh], uc = u_cross[hh];

    // ---- stage Q tile transposed: Qs[d][qi] ----
    {
        const float* qbase = q + ((size_t)(b * SS + q0)) * DD + hh * HD;
#pragma unroll
        for (int r = 0; r < 4; r++) {
            int idx = tid + r * 256;      // 1024 float4s
            int qi  = idx >> 4;
            int c4  = (idx & 15) * 4;
            float4 a = *(const float4*)(qbase + (size_t)qi * DD + c4);
            Qs[(c4 + 0) * 64 + qi] = a.x;
            Qs[(c4 + 1) * 64 + qi] = a.y;
            Qs[(c4 + 2) * 64 + qi] = a.z;
            Qs[(c4 + 3) * 64 + qi] = a.w;
        }
    }

    // per-row (query) state
    int   vq[4];
    float m[4], l[4];
    float oacc[4][4];
#pragma unroll
    for (int i = 0; i < 4; i++) {
        vq[i] = vids[b * SS + q0 + ty * 4 + i];
        m[i] = -1e30f;
        l[i] = 0.0f;
#pragma unroll
        for (int j = 0; j < 4; j++) oacc[i][j] = 0.0f;
    }
    __syncthreads();   // Qs ready

    for (int kt = 0; kt < SS; kt += 64) {
        // ---- stage K (transposed) and V (natural) tiles ----
        const float* kbase = k + ((size_t)(b * SS + kt)) * DD + hh * HD;
        const float* vbase = v + ((size_t)(b * SS + kt)) * DD + hh * HD;
#pragma unroll
        for (int r = 0; r < 4; r++) {
            int idx = tid + r * 256;
            int ki  = idx >> 4;
            int c4  = (idx & 15) * 4;
            float4 a = *(const float4*)(kbase + (size_t)ki * DD + c4);
            Ks[(c4 + 0) * 64 + ki] = a.x;
            Ks[(c4 + 1) * 64 + ki] = a.y;
            Ks[(c4 + 2) * 64 + ki] = a.z;
            Ks[(c4 + 3) * 64 + ki] = a.w;
            float4 b4 = *(const float4*)(vbase + (size_t)ki * DD + c4);
            *(float4*)&Vs[ki * 64 + c4] = b4;
        }
        if (tid < 64) {
            svid[tid]   = vids[b * SS + kt + tid];
            smaskv[tid] = (1.0f - mask[b * SS + kt + tid]) * -1e9f;
        }
        __syncthreads();

        // ---- S = Q @ K^T : 64x64x64 microtiled GEMM ----
        float s[4][4];
#pragma unroll
        for (int i = 0; i < 4; i++)
#pragma unroll
            for (int j = 0; j < 4; j++) s[i][j] = 0.0f;
#pragma unroll 8
        for (int kk = 0; kk < 64; kk++) {
            float4 ra = *(const float4*)&Qs[kk * 64 + ty * 4];
            float4 rb = *(const float4*)&Ks[kk * 64 + tx * 4];
            float a0 = ra.x, a1 = ra.y, a2 = ra.z, a3 = ra.w;
            float b0 = rb.x, b1 = rb.y, b2 = rb.z, b3 = rb.w;
            s[0][0] += a0 * b0; s[0][1] += a0 * b1; s[0][2] += a0 * b2; s[0][3] += a0 * b3;
            s[1][0] += a1 * b0; s[1][1] += a1 * b1; s[1][2] += a1 * b2; s[1][3] += a1 * b3;
            s[2][0] += a2 * b0; s[2][1] += a2 * b1; s[2][2] += a2 * b2; s[2][3] += a2 * b3;
            s[3][0] += a3 * b0; s[3][1] += a3 * b1; s[3][2] += a3 * b2; s[3][3] += a3 * b3;
        }

        // ---- bias + online softmax (row spread over 16 tx lanes) ----
#pragma unroll
        for (int i = 0; i < 4; i++) {
            float rmax = -1e30f;
#pragma unroll
            for (int j = 0; j < 4; j++) {
                int c = tx * 4 + j;
                float sc = s[i][j] * 0.125f + (svid[c] == vq[i] ? us : uc) + smaskv[c];
                s[i][j] = sc;
                rmax = fmaxf(rmax, sc);
            }
            rmax = fmaxf(rmax, __shfl_xor_sync(0xFFFFFFFF, rmax, 1));
            rmax = fmaxf(rmax, __shfl_xor_sync(0xFFFFFFFF, rmax, 2));
            rmax = fmaxf(rmax, __shfl_xor_sync(0xFFFFFFFF, rmax, 4));
            rmax = fmaxf(rmax, __shfl_xor_sync(0xFFFFFFFF, rmax, 8));
            float newm = fmaxf(m[i], rmax);
            float corr = __expf(m[i] - newm);
            m[i] = newm;
            float rsum = 0.0f;
#pragma unroll
            for (int j = 0; j < 4; j++) {
                float p = __expf(s[i][j] - newm);
                s[i][j] = p;
                rsum += p;
            }
            rsum += __shfl_xor_sync(0xFFFFFFFF, rsum, 1);
            rsum += __shfl_xor_sync(0xFFFFFFFF, rsum, 2);
            rsum += __shfl_xor_sync(0xFFFFFFFF, rsum, 4);
            rsum += __shfl_xor_sync(0xFFFFFFFF, rsum, 8);
            l[i] = l[i] * corr + rsum;
#pragma unroll
            for (int j = 0; j < 4; j++) {
                oacc[i][j] *= corr;
                Ps[(tx * 4 + j) * 68 + ty * 4 + i] = s[i][j];
            }
        }
        __syncthreads();   // Ps visible

        // ---- O += P @ V : 64x64x64 microtiled GEMM ----
#pragma unroll 8
        for (int cc = 0; cc < 64; cc++) {
            float4 ra = *(const float4*)&Ps[cc * 68 + ty * 4];
            float4 rb = *(const float4*)&Vs[cc * 64 + tx * 4];
            float a0 = ra.x, a1 = ra.y, a2 = ra.z, a3 = ra.w;
            float b0 = rb.x, b1 = rb.y, b2 = rb.z, b3 = rb.w;
            oacc[0][0] += a0 * b0; oacc[0][1] += a0 * b1; oacc[0][2] += a0 * b2; oacc[0][3] += a0 * b3;
            oacc[1][0] += a1 * b0; oacc[1][1] += a1 * b1; oacc[1][2] += a1 * b2; oacc[1][3] += a1 * b3;
            oacc[2][0] += a2 * b0; oacc[2][1] += a2 * b1; oacc[2][2] += a2 * b2; oacc[2][3] += a2 * b3;
            oacc[3][0] += a3 * b0; oacc[3][1] += a3 * b1; oacc[3][2] += a3 * b2; oacc[3][3] += a3 * b3;
        }
        __syncthreads();   // done with Ks/Vs/Ps before next tile overwrites
    }

    // ---- write O / l ----
#pragma unroll
    for (int i = 0; i < 4; i++) {
        float invl = 1.0f / l[i];
        float4 r;
        r.x = oacc[i][0] * invl;
        r.y = oacc[i][1] * invl;
        r.z = oacc[i][2] * invl;
        r.w = oacc[i][3] * invl;
        float* op = o + ((size_t)(b * SS + q0 + ty * 4 + i)) * DD + hh * HD + tx * 4;
        *(float4*)op = r;
    }
}

// ---------------- driver -----------------------------------------------------
extern "C" void kernel_launch(void* const* d_in, const int* in_sizes, int n_in,
                              void* d_out, int out_size) {
    const float* x      = (const float*)d_in[0];
    const int*   vids   = (const int*)  d_in[1];
    const float* mask   = (const float*)d_in[2];
    const float* W_pe   = (const float*)d_in[3];
    const float* b_pe   = (const float*)d_in[4];
    const float* Wq     = (const float*)d_in[5];
    const float* bq     = (const float*)d_in[6];
    const float* Wk     = (const float*)d_in[7];
    const float* bk     = (const float*)d_in[8];
    const float* Wv     = (const float*)d_in[9];
    const float* bv     = (const float*)d_in[10];
    const float* Wo     = (const float*)d_in[11];
    const float* bo     = (const float*)d_in[12];
    const float* u_same = (const float*)d_in[13];
    const float* u_cross= (const float*)d_in[14];
    const float* g1     = (const float*)d_in[15];
    const float* be1    = (const float*)d_in[16];
    const float* W1     = (const float*)d_in[17];
    const float* b1f    = (const float*)d_in[18];
    const float* W2     = (const float*)d_in[19];
    const float* b2f    = (const float*)d_in[20];
    const float* g2     = (const float*)d_in[21];
    const float* be2    = (const float*)d_in[22];
    const float* Wh     = (const float*)d_in[23];
    const float* bh     = (const float*)d_in[24];
    float* out = (float*)d_out;

    float *ph, *pq, *pk, *pv, *po, *pt, *pff, *pc, *ps;
    cudaGetSymbolAddress((void**)&ph,  g_h);
    cudaGetSymbolAddress((void**)&pq,  g_q);
    cudaGetSymbolAddress((void**)&pk,  g_k);
    cudaGetSymbolAddress((void**)&pv,  g_v);
    cudaGetSymbolAddress((void**)&po,  g_o);
    cudaGetSymbolAddress((void**)&pt,  g_t);
    cudaGetSymbolAddress((void**)&pff, g_ff);
    cudaGetSymbolAddress((void**)&pc,  g_cos);
    cudaGetSymbolAddress((void**)&ps,  g_sin);

    static int smem_set = 0;
    if (!smem_set) {
        cudaFuncSetAttribute(attn2_kernel, cudaFuncAttributeMaxDynamicSharedMemorySize,
                             ATTN_SMEM_FLOATS * 4);
        smem_set = 1;
    }

    rope_tables_kernel<<<(SS * 32 + 255) / 256, 256>>>(pc, ps);
    sgemm_bias<0><<<dim3(DD / 128, MM / 128), 256>>>(x, W_pe, b_pe, ph, MM, DD, PP);

    for (int l = 0; l < LL; l++) {
        const float* Wql = Wq + (size_t)l * DD * DD;
        const float* Wkl = Wk + (size_t)l * DD * DD;
        const float* Wvl = Wv + (size_t)l * DD * DD;
        const float* Wol = Wo + (size_t)l * DD * DD;
        const float* W1l = W1 + (size_t)l * DD * DF;
        const float* W2l = W2 + (size_t)l * DF * DD;

        sgemm_bias<0><<<dim3(DD / 128, MM / 128), 256>>>(ph, Wql, bq + l * DD, pq, MM, DD, DD);
        sgemm_bias<0><<<dim3(DD / 128, MM / 128), 256>>>(ph, Wkl, bk + l * DD, pk, MM, DD, DD);
        sgemm_bias<0><<<dim3(DD / 128, MM / 128), 256>>>(ph, Wvl, bv + l * DD, pv, MM, DD, DD);

        rope_apply_kernel<<<(MM * HH * 32) / 256, 256>>>(pq, pc, ps);
        rope_apply_kernel<<<(MM * HH * 32) / 256, 256>>>(pk, pc, ps);

        attn2_kernel<<<BB * HH * (SS / 64), 256, ATTN_SMEM_FLOATS * 4>>>(
            pq, pk, pv, vids, mask, u_same + l * HH, u_cross + l * HH, po);

        sgemm_bias<0><<<dim3(DD / 128, MM / 128), 256>>>(po, Wol, bo + l * DD, pt, MM, DD, DD);
        add_ln_kernel<<<MM, 128>>>(ph, pt, g1 + l * DD, be1 + l * DD);

        sgemm_bias<1><<<dim3(DF / 128, MM / 128), 256>>>(ph, W1l, b1f + l * DF, pff, MM, DF, DD);
        sgemm_bias<0><<<dim3(DD / 128, MM / 128), 256>>>(pff, W2l, b2f + l * DD, pt, MM, DD, DF);
        add_ln_kernel<<<MM, 128>>>(ph, pt, g2 + l * DD, be2 + l * DD);
    }

    head_gemm_kernel<<<(MM * PP) / 256, 256>>>(ph, Wh, bh, out);
}

// round 3
// speedup vs baseline: 4.0575x; 1.4891x over previous
#include <cuda_runtime.h>
#include <math.h>
#include <stdint.h>

#define BB  4
#define SS  2048
#define PP  32
#define DD  512
#define HH  8
#define LL  2
#define DF  2048
#define HD  64
#define MM  (BB*SS)   /* 8192 rows */

// ---------------- scratch (device globals; no allocations allowed) ----------
__device__ float g_h [MM*DD];
__device__ float g_q [MM*DD];
__device__ float g_k [MM*DD];
__device__ float g_v [MM*DD];
__device__ float g_o [MM*DD];
__device__ float g_t [MM*DD];
__device__ float g_ff[MM*DF];
__device__ float g_cos[SS*32];
__device__ float g_sin[SS*32];

// ---------------- RoPE tables ----------------------------------------------
__global__ void rope_tables_kernel(float* __restrict__ ct, float* __restrict__ st) {
    int idx = blockIdx.x * blockDim.x + threadIdx.x;
    if (idx >= SS * 32) return;
    int pos = idx >> 5;
    int i   = idx & 31;
    int fidx = (2 * i) & 31;
    float ex  = (float)(2 * fidx) / 64.0f;
    float inv = 1.0f / powf(10000.0f, ex);
    float ang = (float)pos * inv;
    ct[idx] = cosf(ang);
    st[idx] = sinf(ang);
}

__global__ void rope_apply_kernel(float* __restrict__ q,
                                  const float* __restrict__ ct,
                                  const float* __restrict__ st) {
    int idx = blockIdx.x * blockDim.x + threadIdx.x;   // MM*HH*32 threads
    int i   = idx & 31;
    int rem = idx >> 5;
    int hh  = rem & (HH - 1);
    int row = rem >> 3;
    int s   = row & (SS - 1);
    float c  = ct[s * 32 + i];
    float sn = st[s * 32 + i];
    float* p = q + (size_t)row * DD + hh * HD + 2 * i;
    float x1 = p[0], x2 = p[1];
    p[0] = x1 * c - x2 * sn;
    p[1] = x1 * sn + x2 * c;
}

// ---------------- TF32 tensor-core GEMM -------------------------------------
// C = A[MxK] @ B[KxN] + bias, optional exact GELU.
// Block 128x128xBK16, 8 warps (2 M x 4 N), warp tile 64x32, mma.m16n8k8.tf32.
// Requires M%128==0, N%128==0, K%16==0.

__device__ __forceinline__ uint32_t f2tf(float f) {
    uint32_t u;
    asm("cvt.rna.tf32.f32 %0, %1;" : "=r"(u) : "f"(f));
    return u;
}

__device__ __forceinline__ void mma_tf32(float* c, const uint32_t* a, const uint32_t* b) {
    asm volatile(
        "mma.sync.aligned.m16n8k8.row.col.f32.tf32.tf32.f32 "
        "{%0,%1,%2,%3}, {%4,%5,%6,%7}, {%8,%9}, {%0,%1,%2,%3};\n"
        : "+f"(c[0]), "+f"(c[1]), "+f"(c[2]), "+f"(c[3])
        : "r"(a[0]), "r"(a[1]), "r"(a[2]), "r"(a[3]), "r"(b[0]), "r"(b[1]));
}

#define AS_STRIDE 20    /* 16 + 4 pad: frag banks 20*g+tg conflict-free */
#define BS_STRIDE 136   /* 128 + 8 pad: frag banks 8*tg+g conflict-free */

template <int GELU>
__global__ void __launch_bounds__(256)
tgemm_bias(const float* __restrict__ A, const float* __restrict__ B,
           const float* __restrict__ bias, float* __restrict__ C,
           int M, int N, int K) {
    __shared__ uint32_t As[128 * AS_STRIDE];   // As[m][k]  (tf32 bits)
    __shared__ uint32_t Bs[16 * BS_STRIDE];    // Bs[k][n]  (tf32 bits)

    const int tid  = threadIdx.x;
    const int warp = tid >> 5;
    const int lane = tid & 31;
    const int g    = lane >> 2;     // group id  (0..7)
    const int tg   = lane & 3;      // thread-in-group (0..3)
    const int wm   = (warp & 1) * 64;   // warp M offset
    const int wn   = (warp >> 1) * 32;  // warp N offset
    const int bx = blockIdx.x, by = blockIdx.y;

    // staging coords
    const int aRow = tid >> 1;             // 0..127
    const int aCol = (tid & 1) * 8;        // 0 or 8
    const int bRow = tid >> 5;             // 0..7 (and +8)
    const int bCol = lane * 4;             // 0..124

    const float* Ap = A + (size_t)(by * 128 + aRow) * K + aCol;
    const float* Bp = B + (size_t)bRow * N + bx * 128 + bCol;
    const size_t Bstep = (size_t)8 * N;

    float acc[4][4][4];
#pragma unroll
    for (int i = 0; i < 4; i++)
#pragma unroll
        for (int j = 0; j < 4; j++)
#pragma unroll
            for (int r = 0; r < 4; r++) acc[i][j][r] = 0.0f;

    // prefetch stage 0
    float4 a0 = *(const float4*)(Ap);
    float4 a1 = *(const float4*)(Ap + 4);
    float4 b0 = *(const float4*)(Bp);
    float4 b1 = *(const float4*)(Bp + Bstep);
    Ap += 16;
    Bp += 2 * Bstep;

    for (int k0 = 0; k0 < K; k0 += 16) {
        // store stage to smem (tf32-rounded)
        uint32_t* asp = &As[aRow * AS_STRIDE + aCol];
        asp[0] = f2tf(a0.x); asp[1] = f2tf(a0.y); asp[2] = f2tf(a0.z); asp[3] = f2tf(a0.w);
        asp[4] = f2tf(a1.x); asp[5] = f2tf(a1.y); asp[6] = f2tf(a1.z); asp[7] = f2tf(a1.w);
        uint32_t* bsp0 = &Bs[bRow * BS_STRIDE + bCol];
        bsp0[0] = f2tf(b0.x); bsp0[1] = f2tf(b0.y); bsp0[2] = f2tf(b0.z); bsp0[3] = f2tf(b0.w);
        uint32_t* bsp1 = &Bs[(bRow + 8) * BS_STRIDE + bCol];
        bsp1[0] = f2tf(b1.x); bsp1[1] = f2tf(b1.y); bsp1[2] = f2tf(b1.z); bsp1[3] = f2tf(b1.w);
        __syncthreads();

        // prefetch next stage
        if (k0 + 16 < K) {
            a0 = *(const float4*)(Ap);
            a1 = *(const float4*)(Ap + 4);
            b0 = *(const float4*)(Bp);
            b1 = *(const float4*)(Bp + Bstep);
            Ap += 16;
            Bp += 2 * Bstep;
        }

        // compute: two k8 steps
#pragma unroll
        for (int ks = 0; ks < 16; ks += 8) {
            uint32_t af[4][4], bf[4][2];
#pragma unroll
            for (int mt = 0; mt < 4; mt++) {
                int m = wm + mt * 16;
                af[mt][0] = As[(m + g)     * AS_STRIDE + ks + tg];
                af[mt][1] = As[(m + g + 8) * AS_STRIDE + ks + tg];
                af[mt][2] = As[(m + g)     * AS_STRIDE + ks + tg + 4];
                af[mt][3] = As[(m + g + 8) * AS_STRIDE + ks + tg + 4];
            }
#pragma unroll
            for (int nt = 0; nt < 4; nt++) {
                int n = wn + nt * 8;
                bf[nt][0] = Bs[(ks + tg)     * BS_STRIDE + n + g];
                bf[nt][1] = Bs[(ks + tg + 4) * BS_STRIDE + n + g];
            }
#pragma unroll
            for (int mt = 0; mt < 4; mt++)
#pragma unroll
                for (int nt = 0; nt < 4; nt++)
                    mma_tf32(acc[mt][nt], af[mt], bf[nt]);
        }
        __syncthreads();
    }

    // epilogue: bias (+GELU), write float2 pairs
#pragma unroll
    for (int mt = 0; mt < 4; mt++) {
#pragma unroll
        for (int nt = 0; nt < 4; nt++) {
            int row0 = by * 128 + wm + mt * 16 + g;
            int col  = bx * 128 + wn + nt * 8 + 2 * tg;
            float bc0 = bias[col], bc1 = bias[col + 1];
            float v0 = acc[mt][nt][0] + bc0;
            float v1 = acc[mt][nt][1] + bc1;
            float v2 = acc[mt][nt][2] + bc0;
            float v3 = acc[mt][nt][3] + bc1;
            if (GELU) {
                v0 = 0.5f * v0 * (1.0f + erff(v0 * 0.70710678118654752f));
                v1 = 0.5f * v1 * (1.0f + erff(v1 * 0.70710678118654752f));
                v2 = 0.5f * v2 * (1.0f + erff(v2 * 0.70710678118654752f));
                v3 = 0.5f * v3 * (1.0f + erff(v3 * 0.70710678118654752f));
            }
            *(float2*)(C + (size_t)row0 * N + col)       = make_float2(v0, v1);
            *(float2*)(C + (size_t)(row0 + 8) * N + col) = make_float2(v2, v3);
        }
    }
}

// ---------------- naive head GEMM: out[M x 32] = h @ Wh + bh ----------------
__global__ void head_gemm_kernel(const float* __restrict__ h,
                                 const float* __restrict__ Wh,
                                 const float* __restrict__ bh,
                                 float* __restrict__ out) {
    int idx = blockIdx.x * blockDim.x + threadIdx.x;
    int n = idx & (PP - 1);
    int m = idx / PP;
    float acc = bh[n];
    const float* hp = h + (size_t)m * DD;
#pragma unroll 8
    for (int k = 0; k < DD; k++) acc += hp[k] * Wh[k * PP + n];
    out[idx] = acc;
}

// ---------------- residual add + LayerNorm (in-place into h) ----------------
__global__ void add_ln_kernel(float* __restrict__ h, const float* __restrict__ d,
                              const float* __restrict__ g, const float* __restrict__ b) {
    int row = blockIdx.x;
    int t   = threadIdx.x;
    float4 hv = *(float4*)(h + (size_t)row * DD + t * 4);
    float4 dv = *(const float4*)(d + (size_t)row * DD + t * 4);
    float v0 = hv.x + dv.x, v1 = hv.y + dv.y, v2 = hv.z + dv.z, v3 = hv.w + dv.w;
    float s  = v0 + v1 + v2 + v3;
    float s2 = v0 * v0 + v1 * v1 + v2 * v2 + v3 * v3;
#pragma unroll
    for (int off = 16; off; off >>= 1) {
        s  += __shfl_xor_sync(0xFFFFFFFF, s,  off);
        s2 += __shfl_xor_sync(0xFFFFFFFF, s2, off);
    }
    __shared__ float sh[8];
    int w = t >> 5, lane = t & 31;
    if (lane == 0) { sh[w] = s; sh[4 + w] = s2; }
    __syncthreads();
    s  = sh[0] + sh[1] + sh[2] + sh[3];
    s2 = sh[4] + sh[5] + sh[6] + sh[7];
    float mean = s * (1.0f / DD);
    float var  = s2 * (1.0f / DD) - mean * mean;
    float inv  = rsqrtf(var + 1e-5f);
    float4 gv = *(const float4*)(g + t * 4);
    float4 bv = *(const float4*)(b + t * 4);
    float4 o;
    o.x = (v0 - mean) * inv * gv.x + bv.x;
    o.y = (v1 - mean) * inv * gv.y + bv.y;
    o.z = (v2 - mean) * inv * gv.z + bv.z;
    o.w = (v3 - mean) * inv * gv.w + bv.w;
    *(float4*)(h + (size_t)row * DD + t * 4) = o;
}

// ---------------- flash attention, tiled GEMM formulation -------------------
#define ATTN_SMEM_FLOATS (16768)

__global__ void __launch_bounds__(256)
attn2_kernel(const float* __restrict__ q, const float* __restrict__ k,
             const float* __restrict__ v, const int* __restrict__ vids,
             const float* __restrict__ mask,
             const float* __restrict__ u_same, const float* __restrict__ u_cross,
             float* __restrict__ o) {
    extern __shared__ float smem[];
    float* Qs = smem;                 // [64][64] (transposed)
    float* Ks = smem + 4096;          // [64][64] (transposed)
    float* Vs = smem + 8192;          // [64][64]
    float* Ps = smem + 12288;         // [64][68]
    int*   svid   = (int*)(smem + 16640);
    float* smaskv = smem + 16704;

    int tid = threadIdx.x;
    int tx = tid & 15;
    int ty = tid >> 4;

    int qt = blockIdx.x & (SS / 64 - 1);
    int bh = blockIdx.x / (SS / 64);
    int hh = bh & (HH - 1);
    int b  = bh / HH;
    int q0 = qt * 64;

    const float us = u_same[hh], uc = u_cross[hh];

    {
        const float* qbase = q + ((size_t)(b * SS + q0)) * DD + hh * HD;
#pragma unroll
        for (int r = 0; r < 4; r++) {
            int idx = tid + r * 256;
            int qi  = idx >> 4;
            int c4  = (idx & 15) * 4;
            float4 a = *(const float4*)(qbase + (size_t)qi * DD + c4);
            Qs[(c4 + 0) * 64 + qi] = a.x;
            Qs[(c4 + 1) * 64 + qi] = a.y;
            Qs[(c4 + 2) * 64 + qi] = a.z;
            Qs[(c4 + 3) * 64 + qi] = a.w;
        }
    }

    int   vq[4];
    float m[4], l[4];
    float oacc[4][4];
#pragma unroll
    for (int i = 0; i < 4; i++) {
        vq[i] = vids[b * SS + q0 + ty * 4 + i];
        m[i] = -1e30f;
        l[i] = 0.0f;
#pragma unroll
        for (int j = 0; j < 4; j++) oacc[i][j] = 0.0f;
    }
    __syncthreads();

    for (int kt = 0; kt < SS; kt += 64) {
        const float* kbase = k + ((size_t)(b * SS + kt)) * DD + hh * HD;
        const float* vbase = v + ((size_t)(b * SS + kt)) * DD + hh * HD;
#pragma unroll
        for (int r = 0; r < 4; r++) {
            int idx = tid + r * 256;
            int ki  = idx >> 4;
            int c4  = (idx & 15) * 4;
            float4 a = *(const float4*)(kbase + (size_t)ki * DD + c4);
            Ks[(c4 + 0) * 64 + ki] = a.x;
            Ks[(c4 + 1) * 64 + ki] = a.y;
            Ks[(c4 + 2) * 64 + ki] = a.z;
            Ks[(c4 + 3) * 64 + ki] = a.w;
            float4 b4 = *(const float4*)(vbase + (size_t)ki * DD + c4);
            *(float4*)&Vs[ki * 64 + c4] = b4;
        }
        if (tid < 64) {
            svid[tid]   = vids[b * SS + kt + tid];
            smaskv[tid] = (1.0f - mask[b * SS + kt + tid]) * -1e9f;
        }
        __syncthreads();

        float s[4][4];
#pragma unroll
        for (int i = 0; i < 4; i++)
#pragma unroll
            for (int j = 0; j < 4; j++) s[i][j] = 0.0f;
#pragma unroll 8
        for (int kk = 0; kk < 64; kk++) {
            float4 ra = *(const float4*)&Qs[kk * 64 + ty * 4];
            float4 rb = *(const float4*)&Ks[kk * 64 + tx * 4];
            float a0 = ra.x, a1 = ra.y, a2 = ra.z, a3 = ra.w;
            float b0 = rb.x, b1 = rb.y, b2 = rb.z, b3 = rb.w;
            s[0][0] += a0 * b0; s[0][1] += a0 * b1; s[0][2] += a0 * b2; s[0][3] += a0 * b3;
            s[1][0] += a1 * b0; s[1][1] += a1 * b1; s[1][2] += a1 * b2; s[1][3] += a1 * b3;
            s[2][0] += a2 * b0; s[2][1] += a2 * b1; s[2][2] += a2 * b2; s[2][3] += a2 * b3;
            s[3][0] += a3 * b0; s[3][1] += a3 * b1; s[3][2] += a3 * b2; s[3][3] += a3 * b3;
        }

#pragma unroll
        for (int i = 0; i < 4; i++) {
            float rmax = -1e30f;
#pragma unroll
            for (int j = 0; j < 4; j++) {
                int c = tx * 4 + j;
                float sc = s[i][j] * 0.125f + (svid[c] == vq[i] ? us : uc) + smaskv[c];
                s[i][j] = sc;
                rmax = fmaxf(rmax, sc);
            }
            rmax = fmaxf(rmax, __shfl_xor_sync(0xFFFFFFFF, rmax, 1));
            rmax = fmaxf(rmax, __shfl_xor_sync(0xFFFFFFFF, rmax, 2));
            rmax = fmaxf(rmax, __shfl_xor_sync(0xFFFFFFFF, rmax, 4));
            rmax = fmaxf(rmax, __shfl_xor_sync(0xFFFFFFFF, rmax, 8));
            float newm = fmaxf(m[i], rmax);
            float corr = __expf(m[i] - newm);
            m[i] = newm;
            float rsum = 0.0f;
#pragma unroll
            for (int j = 0; j < 4; j++) {
                float p = __expf(s[i][j] - newm);
                s[i][j] = p;
                rsum += p;
            }
            rsum += __shfl_xor_sync(0xFFFFFFFF, rsum, 1);
            rsum += __shfl_xor_sync(0xFFFFFFFF, rsum, 2);
            rsum += __shfl_xor_sync(0xFFFFFFFF, rsum, 4);
            rsum += __shfl_xor_sync(0xFFFFFFFF, rsum, 8);
            l[i] = l[i] * corr + rsum;
#pragma unroll
            for (int j = 0; j < 4; j++) {
                oacc[i][j] *= corr;
                Ps[(tx * 4 + j) * 68 + ty * 4 + i] = s[i][j];
            }
        }
        __syncthreads();

#pragma unroll 8
        for (int cc = 0; cc < 64; cc++) {
            float4 ra = *(const float4*)&Ps[cc * 68 + ty * 4];
            float4 rb = *(const float4*)&Vs[cc * 64 + tx * 4];
            float a0 = ra.x, a1 = ra.y, a2 = ra.z, a3 = ra.w;
            float b0 = rb.x, b1 = rb.y, b2 = rb.z, b3 = rb.w;
            oacc[0][0] += a0 * b0; oacc[0][1] += a0 * b1; oacc[0][2] += a0 * b2; oacc[0][3] += a0 * b3;
            oacc[1][0] += a1 * b0; oacc[1][1] += a1 * b1; oacc[1][2] += a1 * b2; oacc[1][3] += a1 * b3;
            oacc[2][0] += a2 * b0; oacc[2][1] += a2 * b1; oacc[2][2] += a2 * b2; oacc[2][3] += a2 * b3;
            oacc[3][0] += a3 * b0; oacc[3][1] += a3 * b1; oacc[3][2] += a3 * b2; oacc[3][3] += a3 * b3;
        }
        __syncthreads();
    }

#pragma unroll
    for (int i = 0; i < 4; i++) {
        float invl = 1.0f / l[i];
        float4 r;
        r.x = oacc[i][0] * invl;
        r.y = oacc[i][1] * invl;
        r.z = oacc[i][2] * invl;
        r.w = oacc[i][3] * invl;
        float* op = o + ((size_t)(b * SS + q0 + ty * 4 + i)) * DD + hh * HD + tx * 4;
        *(float4*)op = r;
    }
}

// ---------------- driver -----------------------------------------------------
extern "C" void kernel_launch(void* const* d_in, const int* in_sizes, int n_in,
                              void* d_out, int out_size) {
    const float* x      = (const float*)d_in[0];
    const int*   vids   = (const int*)  d_in[1];
    const float* mask   = (const float*)d_in[2];
    const float* W_pe   = (const float*)d_in[3];
    const float* b_pe   = (const float*)d_in[4];
    const float* Wq     = (const float*)d_in[5];
    const float* bq     = (const float*)d_in[6];
    const float* Wk     = (const float*)d_in[7];
    const float* bk     = (const float*)d_in[8];
    const float* Wv     = (const float*)d_in[9];
    const float* bv     = (const float*)d_in[10];
    const float* Wo     = (const float*)d_in[11];
    const float* bo     = (const float*)d_in[12];
    const float* u_same = (const float*)d_in[13];
    const float* u_cross= (const float*)d_in[14];
    const float* g1     = (const float*)d_in[15];
    const float* be1    = (const float*)d_in[16];
    const float* W1     = (const float*)d_in[17];
    const float* b1f    = (const float*)d_in[18];
    const float* W2     = (const float*)d_in[19];
    const float* b2f    = (const float*)d_in[20];
    const float* g2     = (const float*)d_in[21];
    const float* be2    = (const float*)d_in[22];
    const float* Wh     = (const float*)d_in[23];
    const float* bh     = (const float*)d_in[24];
    float* out = (float*)d_out;

    float *ph, *pq, *pk, *pv, *po, *pt, *pff, *pc, *ps;
    cudaGetSymbolAddress((void**)&ph,  g_h);
    cudaGetSymbolAddress((void**)&pq,  g_q);
    cudaGetSymbolAddress((void**)&pk,  g_k);
    cudaGetSymbolAddress((void**)&pv,  g_v);
    cudaGetSymbolAddress((void**)&po,  g_o);
    cudaGetSymbolAddress((void**)&pt,  g_t);
    cudaGetSymbolAddress((void**)&pff, g_ff);
    cudaGetSymbolAddress((void**)&pc,  g_cos);
    cudaGetSymbolAddress((void**)&ps,  g_sin);

    static int smem_set = 0;
    if (!smem_set) {
        cudaFuncSetAttribute(attn2_kernel, cudaFuncAttributeMaxDynamicSharedMemorySize,
                             ATTN_SMEM_FLOATS * 4);
        smem_set = 1;
    }

    rope_tables_kernel<<<(SS * 32 + 255) / 256, 256>>>(pc, ps);
    tgemm_bias<0><<<dim3(DD / 128, MM / 128), 256>>>(x, W_pe, b_pe, ph, MM, DD, PP);

    for (int l = 0; l < LL; l++) {
        const float* Wql = Wq + (size_t)l * DD * DD;
        const float* Wkl = Wk + (size_t)l * DD * DD;
        const float* Wvl = Wv + (size_t)l * DD * DD;
        const float* Wol = Wo + (size_t)l * DD * DD;
        const float* W1l = W1 + (size_t)l * DD * DF;
        const float* W2l = W2 + (size_t)l * DF * DD;

        tgemm_bias<0><<<dim3(DD / 128, MM / 128), 256>>>(ph, Wql, bq + l * DD, pq, MM, DD, DD);
        tgemm_bias<0><<<dim3(DD / 128, MM / 128), 256>>>(ph, Wkl, bk + l * DD, pk, MM, DD, DD);
        tgemm_bias<0><<<dim3(DD / 128, MM / 128), 256>>>(ph, Wvl, bv + l * DD, pv, MM, DD, DD);

        rope_apply_kernel<<<(MM * HH * 32) / 256, 256>>>(pq, pc, ps);
        rope_apply_kernel<<<(MM * HH * 32) / 256, 256>>>(pk, pc, ps);

        attn2_kernel<<<BB * HH * (SS / 64), 256, ATTN_SMEM_FLOATS * 4>>>(
            pq, pk, pv, vids, mask, u_same + l * HH, u_cross + l * HH, po);

        tgemm_bias<0><<<dim3(DD / 128, MM / 128), 256>>>(po, Wol, bo + l * DD, pt, MM, DD, DD);
        add_ln_kernel<<<MM, 128>>>(ph, pt, g1 + l * DD, be1 + l * DD);

        tgemm_bias<1><<<dim3(DF / 128, MM / 128), 256>>>(ph, W1l, b1f + l * DF, pff, MM, DF, DD);
        tgemm_bias<0><<<dim3(DD / 128, MM / 128), 256>>>(pff, W2l, b2f + l * DD, pt, MM, DD, DF);
        add_ln_kernel<<<MM, 128>>>(ph, pt, g2 + l * DD, be2 + l * DD);
    }

    head_gemm_kernel<<<(MM * PP) / 256, 256>>>(ph, Wh, bh, out);
}

// round 4
// speedup vs baseline: 8.0493x; 1.9838x over previous
#include <cuda_runtime.h>
#include <math.h>
#include <stdint.h>

#define BB  4
#define SS  2048
#define PP  32
#define DD  512
#define HH  8
#define LL  2
#define DF  2048
#define HD  64
#define MM  (BB*SS)   /* 8192 rows */

// ---------------- scratch (device globals; no allocations allowed) ----------
__device__ float g_h [MM*DD];
__device__ float g_q [MM*DD];
__device__ float g_k [MM*DD];
__device__ float g_v [MM*DD];
__device__ float g_o [MM*DD];
__device__ float g_t [MM*DD];
__device__ float g_ff[MM*DF];
__device__ float g_cos[SS*32];
__device__ float g_sin[SS*32];

// ---------------- RoPE tables ----------------------------------------------
__global__ void rope_tables_kernel(float* __restrict__ ct, float* __restrict__ st) {
    int idx = blockIdx.x * blockDim.x + threadIdx.x;
    if (idx >= SS * 32) return;
    int pos = idx >> 5;
    int i   = idx & 31;
    int fidx = (2 * i) & 31;
    float ex  = (float)(2 * fidx) / 64.0f;
    float inv = 1.0f / powf(10000.0f, ex);
    float ang = (float)pos * inv;
    ct[idx] = cosf(ang);
    st[idx] = sinf(ang);
}

__global__ void rope_apply_kernel(float* __restrict__ q,
                                  const float* __restrict__ ct,
                                  const float* __restrict__ st) {
    int idx = blockIdx.x * blockDim.x + threadIdx.x;   // MM*HH*32 threads
    int i   = idx & 31;
    int rem = idx >> 5;
    int hh  = rem & (HH - 1);
    int row = rem >> 3;
    int s   = row & (SS - 1);
    float c  = ct[s * 32 + i];
    float sn = st[s * 32 + i];
    float* p = q + (size_t)row * DD + hh * HD + 2 * i;
    float x1 = p[0], x2 = p[1];
    p[0] = x1 * c - x2 * sn;
    p[1] = x1 * sn + x2 * c;
}

// ---------------- tf32 helpers ----------------------------------------------
__device__ __forceinline__ uint32_t f2tf(float f) {
    uint32_t u;
    asm("cvt.rna.tf32.f32 %0, %1;" : "=r"(u) : "f"(f));
    return u;
}

__device__ __forceinline__ void mma_tf32(float* c, const uint32_t* a, const uint32_t* b) {
    asm volatile(
        "mma.sync.aligned.m16n8k8.row.col.f32.tf32.tf32.f32 "
        "{%0,%1,%2,%3}, {%4,%5,%6,%7}, {%8,%9}, {%0,%1,%2,%3};\n"
        : "+f"(c[0]), "+f"(c[1]), "+f"(c[2]), "+f"(c[3])
        : "r"(a[0]), "r"(a[1]), "r"(a[2]), "r"(a[3]), "r"(b[0]), "r"(b[1]));
}

// ---------------- TF32 tensor-core GEMM -------------------------------------
#define AS_STRIDE 20
#define BS_STRIDE 136

template <int GELU>
__global__ void __launch_bounds__(256)
tgemm_bias(const float* __restrict__ A, const float* __restrict__ B,
           const float* __restrict__ bias, float* __restrict__ C,
           int M, int N, int K) {
    __shared__ uint32_t As[128 * AS_STRIDE];
    __shared__ uint32_t Bs[16 * BS_STRIDE];

    const int tid  = threadIdx.x;
    const int warp = tid >> 5;
    const int lane = tid & 31;
    const int g    = lane >> 2;
    const int tg   = lane & 3;
    const int wm   = (warp & 1) * 64;
    const int wn   = (warp >> 1) * 32;
    const int bx = blockIdx.x, by = blockIdx.y;

    const int aRow = tid >> 1;
    const int aCol = (tid & 1) * 8;
    const int bRow = tid >> 5;
    const int bCol = lane * 4;

    const float* Ap = A + (size_t)(by * 128 + aRow) * K + aCol;
    const float* Bp = B + (size_t)bRow * N + bx * 128 + bCol;
    const size_t Bstep = (size_t)8 * N;

    float acc[4][4][4];
#pragma unroll
    for (int i = 0; i < 4; i++)
#pragma unroll
        for (int j = 0; j < 4; j++)
#pragma unroll
            for (int r = 0; r < 4; r++) acc[i][j][r] = 0.0f;

    float4 a0 = *(const float4*)(Ap);
    float4 a1 = *(const float4*)(Ap + 4);
    float4 b0 = *(const float4*)(Bp);
    float4 b1 = *(const float4*)(Bp + Bstep);
    Ap += 16;
    Bp += 2 * Bstep;

    for (int k0 = 0; k0 < K; k0 += 16) {
        uint32_t* asp = &As[aRow * AS_STRIDE + aCol];
        asp[0] = f2tf(a0.x); asp[1] = f2tf(a0.y); asp[2] = f2tf(a0.z); asp[3] = f2tf(a0.w);
        asp[4] = f2tf(a1.x); asp[5] = f2tf(a1.y); asp[6] = f2tf(a1.z); asp[7] = f2tf(a1.w);
        uint32_t* bsp0 = &Bs[bRow * BS_STRIDE + bCol];
        bsp0[0] = f2tf(b0.x); bsp0[1] = f2tf(b0.y); bsp0[2] = f2tf(b0.z); bsp0[3] = f2tf(b0.w);
        uint32_t* bsp1 = &Bs[(bRow + 8) * BS_STRIDE + bCol];
        bsp1[0] = f2tf(b1.x); bsp1[1] = f2tf(b1.y); bsp1[2] = f2tf(b1.z); bsp1[3] = f2tf(b1.w);
        __syncthreads();

        if (k0 + 16 < K) {
            a0 = *(const float4*)(Ap);
            a1 = *(const float4*)(Ap + 4);
            b0 = *(const float4*)(Bp);
            b1 = *(const float4*)(Bp + Bstep);
            Ap += 16;
            Bp += 2 * Bstep;
        }

#pragma unroll
        for (int ks = 0; ks < 16; ks += 8) {
            uint32_t af[4][4], bf[4][2];
#pragma unroll
            for (int mt = 0; mt < 4; mt++) {
                int m = wm + mt * 16;
                af[mt][0] = As[(m + g)     * AS_STRIDE + ks + tg];
                af[mt][1] = As[(m + g + 8) * AS_STRIDE + ks + tg];
                af[mt][2] = As[(m + g)     * AS_STRIDE + ks + tg + 4];
                af[mt][3] = As[(m + g + 8) * AS_STRIDE + ks + tg + 4];
            }
#pragma unroll
            for (int nt = 0; nt < 4; nt++) {
                int n = wn + nt * 8;
                bf[nt][0] = Bs[(ks + tg)     * BS_STRIDE + n + g];
                bf[nt][1] = Bs[(ks + tg + 4) * BS_STRIDE + n + g];
            }
#pragma unroll
            for (int mt = 0; mt < 4; mt++)
#pragma unroll
                for (int nt = 0; nt < 4; nt++)
                    mma_tf32(acc[mt][nt], af[mt], bf[nt]);
        }
        __syncthreads();
    }

#pragma unroll
    for (int mt = 0; mt < 4; mt++) {
#pragma unroll
        for (int nt = 0; nt < 4; nt++) {
            int row0 = by * 128 + wm + mt * 16 + g;
            int col  = bx * 128 + wn + nt * 8 + 2 * tg;
            float bc0 = bias[col], bc1 = bias[col + 1];
            float v0 = acc[mt][nt][0] + bc0;
            float v1 = acc[mt][nt][1] + bc1;
            float v2 = acc[mt][nt][2] + bc0;
            float v3 = acc[mt][nt][3] + bc1;
            if (GELU) {
                v0 = 0.5f * v0 * (1.0f + erff(v0 * 0.70710678118654752f));
                v1 = 0.5f * v1 * (1.0f + erff(v1 * 0.70710678118654752f));
                v2 = 0.5f * v2 * (1.0f + erff(v2 * 0.70710678118654752f));
                v3 = 0.5f * v3 * (1.0f + erff(v3 * 0.70710678118654752f));
            }
            *(float2*)(C + (size_t)row0 * N + col)       = make_float2(v0, v1);
            *(float2*)(C + (size_t)(row0 + 8) * N + col) = make_float2(v2, v3);
        }
    }
}

// ---------------- naive head GEMM: out[M x 32] = h @ Wh + bh ----------------
__global__ void head_gemm_kernel(const float* __restrict__ h,
                                 const float* __restrict__ Wh,
                                 const float* __restrict__ bh,
                                 float* __restrict__ out) {
    int idx = blockIdx.x * blockDim.x + threadIdx.x;
    int n = idx & (PP - 1);
    int m = idx / PP;
    float acc = bh[n];
    const float* hp = h + (size_t)m * DD;
#pragma unroll 8
    for (int k = 0; k < DD; k++) acc += hp[k] * Wh[k * PP + n];
    out[idx] = acc;
}

// ---------------- residual add + LayerNorm (in-place into h) ----------------
__global__ void add_ln_kernel(float* __restrict__ h, const float* __restrict__ d,
                              const float* __restrict__ g, const float* __restrict__ b) {
    int row = blockIdx.x;
    int t   = threadIdx.x;
    float4 hv = *(float4*)(h + (size_t)row * DD + t * 4);
    float4 dv = *(const float4*)(d + (size_t)row * DD + t * 4);
    float v0 = hv.x + dv.x, v1 = hv.y + dv.y, v2 = hv.z + dv.z, v3 = hv.w + dv.w;
    float s  = v0 + v1 + v2 + v3;
    float s2 = v0 * v0 + v1 * v1 + v2 * v2 + v3 * v3;
#pragma unroll
    for (int off = 16; off; off >>= 1) {
        s  += __shfl_xor_sync(0xFFFFFFFF, s,  off);
        s2 += __shfl_xor_sync(0xFFFFFFFF, s2, off);
    }
    __shared__ float sh[8];
    int w = t >> 5, lane = t & 31;
    if (lane == 0) { sh[w] = s; sh[4 + w] = s2; }
    __syncthreads();
    s  = sh[0] + sh[1] + sh[2] + sh[3];
    s2 = sh[4] + sh[5] + sh[6] + sh[7];
    float mean = s * (1.0f / DD);
    float var  = s2 * (1.0f / DD) - mean * mean;
    float inv  = rsqrtf(var + 1e-5f);
    float4 gv = *(const float4*)(g + t * 4);
    float4 bv = *(const float4*)(b + t * 4);
    float4 o;
    o.x = (v0 - mean) * inv * gv.x + bv.x;
    o.y = (v1 - mean) * inv * gv.y + bv.y;
    o.z = (v2 - mean) * inv * gv.z + bv.z;
    o.w = (v3 - mean) * inv * gv.w + bv.w;
    *(float4*)(h + (size_t)row * DD + t * 4) = o;
}

// ---------------- tf32 tensor-core flash attention ---------------------------
// Block = 64 queries of one (b,h); 4 warps; warp tile 16q x 64keys.
// smem (uint32 units):
//   Qs [64][68]   0      (tf32, row-major [q][d])
//   Ks [64][68]   4352   (tf32, row-major [key][d])
//   Vs [64][72]   8704   (tf32, row-major [key][d], stride 72 for B-frag banks)
//   Ps [64][68]   13312  (tf32, row-major [q][key])
//   svid[64]      17664
//   smask[64]     17728
#define ATTN_SMEM_U32 17792
#define QST 68
#define VST 72

__global__ void __launch_bounds__(128)
attn3_kernel(const float* __restrict__ q, const float* __restrict__ k,
             const float* __restrict__ v, const int* __restrict__ vids,
             const float* __restrict__ mask,
             const float* __restrict__ u_same, const float* __restrict__ u_cross,
             float* __restrict__ o) {
    extern __shared__ uint32_t sm[];
    uint32_t* Qs = sm;
    uint32_t* Ks = sm + 4352;
    uint32_t* Vs = sm + 8704;
    uint32_t* Ps = sm + 13312;
    int*   svid  = (int*)(sm + 17664);
    float* smask = (float*)(sm + 17728);

    const int tid  = threadIdx.x;
    const int warp = tid >> 5;
    const int lane = tid & 31;
    const int g    = lane >> 2;
    const int tg   = lane & 3;
    const int qw   = warp * 16;

    int qt = blockIdx.x & (SS / 64 - 1);
    int bh = blockIdx.x / (SS / 64);
    int hh = bh & (HH - 1);
    int b  = bh / HH;
    int q0 = qt * 64;

    const float us = u_same[hh], uc = u_cross[hh];

    // ---- stage Q (row-major tf32) ----
    {
        const float* qbase = q + ((size_t)(b * SS + q0)) * DD + hh * HD;
#pragma unroll
        for (int r = 0; r < 8; r++) {
            int idx = tid + r * 128;
            int qi  = idx >> 4;
            int c4  = (idx & 15) * 4;
            float4 a = *(const float4*)(qbase + (size_t)qi * DD + c4);
            uint4 u = make_uint4(f2tf(a.x), f2tf(a.y), f2tf(a.z), f2tf(a.w));
            *(uint4*)&Qs[qi * QST + c4] = u;
        }
    }

    int vq0 = vids[b * SS + q0 + qw + g];
    int vq1 = vids[b * SS + q0 + qw + g + 8];
    float m0 = -1e30f, m1 = -1e30f, l0 = 0.0f, l1 = 0.0f;
    float oacc[8][4];
#pragma unroll
    for (int nt = 0; nt < 8; nt++)
#pragma unroll
        for (int r = 0; r < 4; r++) oacc[nt][r] = 0.0f;
    __syncthreads();

    for (int kt = 0; kt < SS; kt += 64) {
        // ---- stage K and V (row-major tf32) ----
        const float* kbase = k + ((size_t)(b * SS + kt)) * DD + hh * HD;
        const float* vbase = v + ((size_t)(b * SS + kt)) * DD + hh * HD;
#pragma unroll
        for (int r = 0; r < 8; r++) {
            int idx = tid + r * 128;
            int ki  = idx >> 4;
            int c4  = (idx & 15) * 4;
            float4 a = *(const float4*)(kbase + (size_t)ki * DD + c4);
            *(uint4*)&Ks[ki * QST + c4] =
                make_uint4(f2tf(a.x), f2tf(a.y), f2tf(a.z), f2tf(a.w));
            float4 bb = *(const float4*)(vbase + (size_t)ki * DD + c4);
            *(uint4*)&Vs[ki * VST + c4] =
                make_uint4(f2tf(bb.x), f2tf(bb.y), f2tf(bb.z), f2tf(bb.w));
        }
        if (tid < 64) {
            svid[tid]  = vids[b * SS + kt + tid];
            smask[tid] = (1.0f - mask[b * SS + kt + tid]) * -1e9f;
        }
        __syncthreads();

        // ---- S = Q @ K^T : warp computes 16x64 ----
        float s[8][4];
#pragma unroll
        for (int nt = 0; nt < 8; nt++)
#pragma unroll
            for (int r = 0; r < 4; r++) s[nt][r] = 0.0f;
#pragma unroll
        for (int ks = 0; ks < 64; ks += 8) {
            uint32_t av[4];
            av[0] = Qs[(qw + g)     * QST + ks + tg];
            av[1] = Qs[(qw + g + 8) * QST + ks + tg];
            av[2] = Qs[(qw + g)     * QST + ks + tg + 4];
            av[3] = Qs[(qw + g + 8) * QST + ks + tg + 4];
#pragma unroll
            for (int nt = 0; nt < 8; nt++) {
                uint32_t bv[2];
                bv[0] = Ks[(nt * 8 + g) * QST + ks + tg];
                bv[1] = Ks[(nt * 8 + g) * QST + ks + tg + 4];
                mma_tf32(s[nt], av, bv);
            }
        }

        // ---- bias + online softmax ----
        float rmax0 = -1e30f, rmax1 = -1e30f;
#pragma unroll
        for (int nt = 0; nt < 8; nt++) {
            int c0 = nt * 8 + 2 * tg;
            int c1 = c0 + 1;
            float bia0 = smask[c0], bia1 = smask[c1];
            s[nt][0] = s[nt][0] * 0.125f + (svid[c0] == vq0 ? us : uc) + bia0;
            s[nt][1] = s[nt][1] * 0.125f + (svid[c1] == vq0 ? us : uc) + bia1;
            s[nt][2] = s[nt][2] * 0.125f + (svid[c0] == vq1 ? us : uc) + bia0;
            s[nt][3] = s[nt][3] * 0.125f + (svid[c1] == vq1 ? us : uc) + bia1;
            rmax0 = fmaxf(rmax0, fmaxf(s[nt][0], s[nt][1]));
            rmax1 = fmaxf(rmax1, fmaxf(s[nt][2], s[nt][3]));
        }
        rmax0 = fmaxf(rmax0, __shfl_xor_sync(0xFFFFFFFF, rmax0, 1));
        rmax0 = fmaxf(rmax0, __shfl_xor_sync(0xFFFFFFFF, rmax0, 2));
        rmax1 = fmaxf(rmax1, __shfl_xor_sync(0xFFFFFFFF, rmax1, 1));
        rmax1 = fmaxf(rmax1, __shfl_xor_sync(0xFFFFFFFF, rmax1, 2));
        float newm0 = fmaxf(m0, rmax0);
        float newm1 = fmaxf(m1, rmax1);
        float corr0 = __expf(m0 - newm0);
        float corr1 = __expf(m1 - newm1);
        m0 = newm0; m1 = newm1;

        float rsum0 = 0.0f, rsum1 = 0.0f;
#pragma unroll
        for (int nt = 0; nt < 8; nt++) {
            float p0 = __expf(s[nt][0] - m0);
            float p1 = __expf(s[nt][1] - m0);
            float p2 = __expf(s[nt][2] - m1);
            float p3 = __expf(s[nt][3] - m1);
            rsum0 += p0 + p1;
            rsum1 += p2 + p3;
            int c0 = nt * 8 + 2 * tg;
            Ps[(qw + g)     * QST + c0]     = f2tf(p0);
            Ps[(qw + g)     * QST + c0 + 1] = f2tf(p1);
            Ps[(qw + g + 8) * QST + c0]     = f2tf(p2);
            Ps[(qw + g + 8) * QST + c0 + 1] = f2tf(p3);
            oacc[nt][0] *= corr0;
            oacc[nt][1] *= corr0;
            oacc[nt][2] *= corr1;
            oacc[nt][3] *= corr1;
        }
        rsum0 += __shfl_xor_sync(0xFFFFFFFF, rsum0, 1);
        rsum0 += __shfl_xor_sync(0xFFFFFFFF, rsum0, 2);
        rsum1 += __shfl_xor_sync(0xFFFFFFFF, rsum1, 1);
        rsum1 += __shfl_xor_sync(0xFFFFFFFF, rsum1, 2);
        l0 = l0 * corr0 + rsum0;
        l1 = l1 * corr1 + rsum1;
        __syncwarp();

        // ---- O += P @ V ----
#pragma unroll
        for (int ks = 0; ks < 64; ks += 8) {
            uint32_t av[4];
            av[0] = Ps[(qw + g)     * QST + ks + tg];
            av[1] = Ps[(qw + g + 8) * QST + ks + tg];
            av[2] = Ps[(qw + g)     * QST + ks + tg + 4];
            av[3] = Ps[(qw + g + 8) * QST + ks + tg + 4];
#pragma unroll
            for (int nt = 0; nt < 8; nt++) {
                uint32_t bv[2];
                bv[0] = Vs[(ks + tg)     * VST + nt * 8 + g];
                bv[1] = Vs[(ks + tg + 4) * VST + nt * 8 + g];
                mma_tf32(oacc[nt], av, bv);
            }
        }
        __syncthreads();
    }

    // ---- write O ----
    float invl0 = 1.0f / l0;
    float invl1 = 1.0f / l1;
    float* ob0 = o + ((size_t)(b * SS + q0 + qw + g)) * DD + hh * HD;
    float* ob1 = ob0 + (size_t)8 * DD;
#pragma unroll
    for (int nt = 0; nt < 8; nt++) {
        int c = nt * 8 + 2 * tg;
        *(float2*)(ob0 + c) = make_float2(oacc[nt][0] * invl0, oacc[nt][1] * invl0);
        *(float2*)(ob1 + c) = make_float2(oacc[nt][2] * invl1, oacc[nt][3] * invl1);
    }
}

// ---------------- driver -----------------------------------------------------
extern "C" void kernel_launch(void* const* d_in, const int* in_sizes, int n_in,
                              void* d_out, int out_size) {
    const float* x      = (const float*)d_in[0];
    const int*   vids   = (const int*)  d_in[1];
    const float* mask   = (const float*)d_in[2];
    const float* W_pe   = (const float*)d_in[3];
    const float* b_pe   = (const float*)d_in[4];
    const float* Wq     = (const float*)d_in[5];
    const float* bq     = (const float*)d_in[6];
    const float* Wk     = (const float*)d_in[7];
    const float* bk     = (const float*)d_in[8];
    const float* Wv     = (const float*)d_in[9];
    const float* bv     = (const float*)d_in[10];
    const float* Wo     = (const float*)d_in[11];
    const float* bo     = (const float*)d_in[12];
    const float* u_same = (const float*)d_in[13];
    const float* u_cross= (const float*)d_in[14];
    const float* g1     = (const float*)d_in[15];
    const float* be1    = (const float*)d_in[16];
    const float* W1     = (const float*)d_in[17];
    const float* b1f    = (const float*)d_in[18];
    const float* W2     = (const float*)d_in[19];
    const float* b2f    = (const float*)d_in[20];
    const float* g2     = (const float*)d_in[21];
    const float* be2    = (const float*)d_in[22];
    const float* Wh     = (const float*)d_in[23];
    const float* bh     = (const float*)d_in[24];
    float* out = (float*)d_out;

    float *ph, *pq, *pk, *pv, *po, *pt, *pff, *pc, *ps;
    cudaGetSymbolAddress((void**)&ph,  g_h);
    cudaGetSymbolAddress((void**)&pq,  g_q);
    cudaGetSymbolAddress((void**)&pk,  g_k);
    cudaGetSymbolAddress((void**)&pv,  g_v);
    cudaGetSymbolAddress((void**)&po,  g_o);
    cudaGetSymbolAddress((void**)&pt,  g_t);
    cudaGetSymbolAddress((void**)&pff, g_ff);
    cudaGetSymbolAddress((void**)&pc,  g_cos);
    cudaGetSymbolAddress((void**)&ps,  g_sin);

    static int smem_set = 0;
    if (!smem_set) {
        cudaFuncSetAttribute(attn3_kernel, cudaFuncAttributeMaxDynamicSharedMemorySize,
                             ATTN_SMEM_U32 * 4);
        smem_set = 1;
    }

    rope_tables_kernel<<<(SS * 32 + 255) / 256, 256>>>(pc, ps);
    tgemm_bias<0><<<dim3(DD / 128, MM / 128), 256>>>(x, W_pe, b_pe, ph, MM, DD, PP);

    for (int l = 0; l < LL; l++) {
        const float* Wql = Wq + (size_t)l * DD * DD;
        const float* Wkl = Wk + (size_t)l * DD * DD;
        const float* Wvl = Wv + (size_t)l * DD * DD;
        const float* Wol = Wo + (size_t)l * DD * DD;
        const float* W1l = W1 + (size_t)l * DD * DF;
        const float* W2l = W2 + (size_t)l * DF * DD;

        tgemm_bias<0><<<dim3(DD / 128, MM / 128), 256>>>(ph, Wql, bq + l * DD, pq, MM, DD, DD);
        tgemm_bias<0><<<dim3(DD / 128, MM / 128), 256>>>(ph, Wkl, bk + l * DD, pk, MM, DD, DD);
        tgemm_bias<0><<<dim3(DD / 128, MM / 128), 256>>>(ph, Wvl, bv + l * DD, pv, MM, DD, DD);

        rope_apply_kernel<<<(MM * HH * 32) / 256, 256>>>(pq, pc, ps);
        rope_apply_kernel<<<(MM * HH * 32) / 256, 256>>>(pk, pc, ps);

        attn3_kernel<<<BB * HH * (SS / 64), 128, ATTN_SMEM_U32 * 4>>>(
            pq, pk, pv, vids, mask, u_same + l * HH, u_cross + l * HH, po);

        tgemm_bias<0><<<dim3(DD / 128, MM / 128), 256>>>(po, Wol, bo + l * DD, pt, MM, DD, DD);
        add_ln_kernel<<<MM, 128>>>(ph, pt, g1 + l * DD, be1 + l * DD);

        tgemm_bias<1><<<dim3(DF / 128, MM / 128), 256>>>(ph, W1l, b1f + l * DF, pff, MM, DF, DD);
        tgemm_bias<0><<<dim3(DD / 128, MM / 128), 256>>>(pff, W2l, b2f + l * DD, pt, MM, DD, DF);
        add_ln_kernel<<<MM, 128>>>(ph, pt, g2 + l * DD, be2 + l * DD);
    }

    head_gemm_kernel<<<(MM * PP) / 256, 256>>>(ph, Wh, bh, out);
}

// round 5
// speedup vs baseline: 8.0761x; 1.0033x over previous
#include <cuda_runtime.h>
#include <math.h>
#include <stdint.h>

#define BB  4
#define SS  2048
#define PP  32
#define DD  512
#define HH  8
#define LL  2
#define DF  2048
#define HD  64
#define MM  (BB*SS)   /* 8192 rows */

// ---------------- scratch (device globals; no allocations allowed) ----------
__device__ float g_h [MM*DD];
__device__ float g_q [MM*DD];
__device__ float g_k [MM*DD];
__device__ float g_v [MM*DD];
__device__ float g_o [MM*DD];
__device__ float g_t [MM*DD];
__device__ float g_ff[MM*DF];
__device__ float g_cos[SS*32];
__device__ float g_sin[SS*32];

// ---------------- RoPE tables ----------------------------------------------
__global__ void rope_tables_kernel(float* __restrict__ ct, float* __restrict__ st) {
    int idx = blockIdx.x * blockDim.x + threadIdx.x;
    if (idx >= SS * 32) return;
    int pos = idx >> 5;
    int i   = idx & 31;
    int fidx = (2 * i) & 31;
    float ex  = (float)(2 * fidx) / 64.0f;
    float inv = 1.0f / powf(10000.0f, ex);
    float ang = (float)pos * inv;
    ct[idx] = cosf(ang);
    st[idx] = sinf(ang);
}

// one launch applies RoPE to both q and k
__global__ void rope_apply_kernel(float* __restrict__ q, float* __restrict__ k,
                                  const float* __restrict__ ct,
                                  const float* __restrict__ st) {
    int gidx = blockIdx.x * blockDim.x + threadIdx.x;   // 2*MM*HH*32 threads
    float* base = (gidx < MM * HH * 32) ? q : k;
    int idx = (gidx < MM * HH * 32) ? gidx : gidx - MM * HH * 32;
    int i   = idx & 31;
    int rem = idx >> 5;
    int hh  = rem & (HH - 1);
    int row = rem >> 3;
    int s   = row & (SS - 1);
    float c  = ct[s * 32 + i];
    float sn = st[s * 32 + i];
    float* p = base + (size_t)row * DD + hh * HD + 2 * i;
    float x1 = p[0], x2 = p[1];
    p[0] = x1 * c - x2 * sn;
    p[1] = x1 * sn + x2 * c;
}

// ---------------- tf32 helpers ----------------------------------------------
__device__ __forceinline__ uint32_t f2tf(float f) {
    uint32_t u;
    asm("cvt.rna.tf32.f32 %0, %1;" : "=r"(u) : "f"(f));
    return u;
}

__device__ __forceinline__ void mma_tf32(float* c, const uint32_t* a, const uint32_t* b) {
    asm volatile(
        "mma.sync.aligned.m16n8k8.row.col.f32.tf32.tf32.f32 "
        "{%0,%1,%2,%3}, {%4,%5,%6,%7}, {%8,%9}, {%0,%1,%2,%3};\n"
        : "+f"(c[0]), "+f"(c[1]), "+f"(c[2]), "+f"(c[3])
        : "r"(a[0]), "r"(a[1]), "r"(a[2]), "r"(a[3]), "r"(b[0]), "r"(b[1]));
}

// ---------------- TF32 tensor-core GEMM, 2-stage smem pipeline ---------------
// C = A[MxK] @ Bsel[KxN] + bias_sel, optional GELU.
// grid.x = 3*ntile for fused QKV (sel = bx/ntile), or ntile with identical ptrs.
// Block 128x128x16, 8 warps, warp tile 64x32, mma.m16n8k8.tf32.
#define AS_STRIDE 20
#define BS_STRIDE 136

template <int GELU>
__global__ void __launch_bounds__(256)
tgemm_bias(const float* __restrict__ A,
           const float* __restrict__ B0, const float* __restrict__ B1,
           const float* __restrict__ B2,
           const float* __restrict__ bias0, const float* __restrict__ bias1,
           const float* __restrict__ bias2,
           float* __restrict__ C0, float* __restrict__ C1, float* __restrict__ C2,
           int M, int N, int K, int ntile) {
    __shared__ uint32_t As[2][128 * AS_STRIDE];
    __shared__ uint32_t Bs[2][16 * BS_STRIDE];

    const int sel = blockIdx.x / ntile;
    const int bx  = blockIdx.x - sel * ntile;
    const int by  = blockIdx.y;
    const float* B    = (sel == 0) ? B0 : (sel == 1) ? B1 : B2;
    const float* bias = (sel == 0) ? bias0 : (sel == 1) ? bias1 : bias2;
    float*       C    = (sel == 0) ? C0 : (sel == 1) ? C1 : C2;

    const int tid  = threadIdx.x;
    const int warp = tid >> 5;
    const int lane = tid & 31;
    const int g    = lane >> 2;
    const int tg   = lane & 3;
    const int wm   = (warp & 1) * 64;
    const int wn   = (warp >> 1) * 32;

    const int aRow = tid >> 1;
    const int aCol = (tid & 1) * 8;
    const int bRow = tid >> 5;
    const int bCol = lane * 4;

    const float* Ap = A + (size_t)(by * 128 + aRow) * K + aCol;
    const float* Bp = B + (size_t)bRow * N + bx * 128 + bCol;
    const size_t Bstep = (size_t)8 * N;

    float acc[4][4][4];
#pragma unroll
    for (int i = 0; i < 4; i++)
#pragma unroll
        for (int j = 0; j < 4; j++)
#pragma unroll
            for (int r = 0; r < 4; r++) acc[i][j][r] = 0.0f;

    // prefetch stage 0 into registers
    float4 a0 = *(const float4*)(Ap);
    float4 a1 = *(const float4*)(Ap + 4);
    float4 b0 = *(const float4*)(Bp);
    float4 b1 = *(const float4*)(Bp + Bstep);
    Ap += 16;
    Bp += 2 * Bstep;

    // store stage 0 to buffer 0
    {
        uint32_t* asp = &As[0][aRow * AS_STRIDE + aCol];
        asp[0] = f2tf(a0.x); asp[1] = f2tf(a0.y); asp[2] = f2tf(a0.z); asp[3] = f2tf(a0.w);
        asp[4] = f2tf(a1.x); asp[5] = f2tf(a1.y); asp[6] = f2tf(a1.z); asp[7] = f2tf(a1.w);
        uint32_t* bsp0 = &Bs[0][bRow * BS_STRIDE + bCol];
        bsp0[0] = f2tf(b0.x); bsp0[1] = f2tf(b0.y); bsp0[2] = f2tf(b0.z); bsp0[3] = f2tf(b0.w);
        uint32_t* bsp1 = &Bs[0][(bRow + 8) * BS_STRIDE + bCol];
        bsp1[0] = f2tf(b1.x); bsp1[1] = f2tf(b1.y); bsp1[2] = f2tf(b1.z); bsp1[3] = f2tf(b1.w);
    }
    __syncthreads();

    const int nIter = K >> 4;
    for (int it = 0; it < nIter; it++) {
        const int buf = it & 1;
        const bool more = (it + 1 < nIter);

        // prefetch next stage into registers (latency hidden by compute below)
        if (more) {
            a0 = *(const float4*)(Ap);
            a1 = *(const float4*)(Ap + 4);
            b0 = *(const float4*)(Bp);
            b1 = *(const float4*)(Bp + Bstep);
            Ap += 16;
            Bp += 2 * Bstep;
        }

        // compute from current buffer
#pragma unroll
        for (int ks = 0; ks < 16; ks += 8) {
            uint32_t af[4][4], bf[4][2];
#pragma unroll
            for (int mt = 0; mt < 4; mt++) {
                int m = wm + mt * 16;
                af[mt][0] = As[buf][(m + g)     * AS_STRIDE + ks + tg];
                af[mt][1] = As[buf][(m + g + 8) * AS_STRIDE + ks + tg];
                af[mt][2] = As[buf][(m + g)     * AS_STRIDE + ks + tg + 4];
                af[mt][3] = As[buf][(m + g + 8) * AS_STRIDE + ks + tg + 4];
            }
#pragma unroll
            for (int nt = 0; nt < 4; nt++) {
                int n = wn + nt * 8;
                bf[nt][0] = Bs[buf][(ks + tg)     * BS_STRIDE + n + g];
                bf[nt][1] = Bs[buf][(ks + tg + 4) * BS_STRIDE + n + g];
            }
#pragma unroll
            for (int mt = 0; mt < 4; mt++)
#pragma unroll
                for (int nt = 0; nt < 4; nt++)
                    mma_tf32(acc[mt][nt], af[mt], bf[nt]);
        }

        // store next stage to the other buffer, then one barrier
        if (more) {
            int nb = buf ^ 1;
            uint32_t* asp = &As[nb][aRow * AS_STRIDE + aCol];
            asp[0] = f2tf(a0.x); asp[1] = f2tf(a0.y); asp[2] = f2tf(a0.z); asp[3] = f2tf(a0.w);
            asp[4] = f2tf(a1.x); asp[5] = f2tf(a1.y); asp[6] = f2tf(a1.z); asp[7] = f2tf(a1.w);
            uint32_t* bsp0 = &Bs[nb][bRow * BS_STRIDE + bCol];
            bsp0[0] = f2tf(b0.x); bsp0[1] = f2tf(b0.y); bsp0[2] = f2tf(b0.z); bsp0[3] = f2tf(b0.w);
            uint32_t* bsp1 = &Bs[nb][(bRow + 8) * BS_STRIDE + bCol];
            bsp1[0] = f2tf(b1.x); bsp1[1] = f2tf(b1.y); bsp1[2] = f2tf(b1.z); bsp1[3] = f2tf(b1.w);
            __syncthreads();
        }
    }

    // epilogue
#pragma unroll
    for (int mt = 0; mt < 4; mt++) {
#pragma unroll
        for (int nt = 0; nt < 4; nt++) {
            int row0 = by * 128 + wm + mt * 16 + g;
            int col  = bx * 128 + wn + nt * 8 + 2 * tg;
            float bc0 = bias[col], bc1 = bias[col + 1];
            float v0 = acc[mt][nt][0] + bc0;
            float v1 = acc[mt][nt][1] + bc1;
            float v2 = acc[mt][nt][2] + bc0;
            float v3 = acc[mt][nt][3] + bc1;
            if (GELU) {
                v0 = 0.5f * v0 * (1.0f + erff(v0 * 0.70710678118654752f));
                v1 = 0.5f * v1 * (1.0f + erff(v1 * 0.70710678118654752f));
                v2 = 0.5f * v2 * (1.0f + erff(v2 * 0.70710678118654752f));
                v3 = 0.5f * v3 * (1.0f + erff(v3 * 0.70710678118654752f));
            }
            *(float2*)(C + (size_t)row0 * N + col)       = make_float2(v0, v1);
            *(float2*)(C + (size_t)(row0 + 8) * N + col) = make_float2(v2, v3);
        }
    }
}

// ---------------- naive head GEMM: out[M x 32] = h @ Wh + bh ----------------
__global__ void head_gemm_kernel(const float* __restrict__ h,
                                 const float* __restrict__ Wh,
                                 const float* __restrict__ bh,
                                 float* __restrict__ out) {
    int idx = blockIdx.x * blockDim.x + threadIdx.x;
    int n = idx & (PP - 1);
    int m = idx / PP;
    float acc = bh[n];
    const float* hp = h + (size_t)m * DD;
#pragma unroll 8
    for (int k = 0; k < DD; k++) acc += hp[k] * Wh[k * PP + n];
    out[idx] = acc;
}

// ---------------- residual add + LayerNorm (in-place into h) ----------------
__global__ void add_ln_kernel(float* __restrict__ h, const float* __restrict__ d,
                              const float* __restrict__ g, const float* __restrict__ b) {
    int row = blockIdx.x;
    int t   = threadIdx.x;
    float4 hv = *(float4*)(h + (size_t)row * DD + t * 4);
    float4 dv = *(const float4*)(d + (size_t)row * DD + t * 4);
    float v0 = hv.x + dv.x, v1 = hv.y + dv.y, v2 = hv.z + dv.z, v3 = hv.w + dv.w;
    float s  = v0 + v1 + v2 + v3;
    float s2 = v0 * v0 + v1 * v1 + v2 * v2 + v3 * v3;
#pragma unroll
    for (int off = 16; off; off >>= 1) {
        s  += __shfl_xor_sync(0xFFFFFFFF, s,  off);
        s2 += __shfl_xor_sync(0xFFFFFFFF, s2, off);
    }
    __shared__ float sh[8];
    int w = t >> 5, lane = t & 31;
    if (lane == 0) { sh[w] = s; sh[4 + w] = s2; }
    __syncthreads();
    s  = sh[0] + sh[1] + sh[2] + sh[3];
    s2 = sh[4] + sh[5] + sh[6] + sh[7];
    float mean = s * (1.0f / DD);
    float var  = s2 * (1.0f / DD) - mean * mean;
    float inv  = rsqrtf(var + 1e-5f);
    float4 gv = *(const float4*)(g + t * 4);
    float4 bv = *(const float4*)(b + t * 4);
    float4 o;
    o.x = (v0 - mean) * inv * gv.x + bv.x;
    o.y = (v1 - mean) * inv * gv.y + bv.y;
    o.z = (v2 - mean) * inv * gv.z + bv.z;
    o.w = (v3 - mean) * inv * gv.w + bv.w;
    *(float4*)(h + (size_t)row * DD + t * 4) = o;
}

// ---------------- tf32 tensor-core flash attention ---------------------------
#define ATTN_SMEM_U32 17792
#define QST 68
#define VST 72

__global__ void __launch_bounds__(128)
attn3_kernel(const float* __restrict__ q, const float* __restrict__ k,
             const float* __restrict__ v, const int* __restrict__ vids,
             const float* __restrict__ mask,
             const float* __restrict__ u_same, const float* __restrict__ u_cross,
             float* __restrict__ o) {
    extern __shared__ uint32_t sm[];
    uint32_t* Qs = sm;
    uint32_t* Ks = sm + 4352;
    uint32_t* Vs = sm + 8704;
    uint32_t* Ps = sm + 13312;
    int*   svid  = (int*)(sm + 17664);
    float* smask = (float*)(sm + 17728);

    const int tid  = threadIdx.x;
    const int warp = tid >> 5;
    const int lane = tid & 31;
    const int g    = lane >> 2;
    const int tg   = lane & 3;
    const int qw   = warp * 16;

    int qt = blockIdx.x & (SS / 64 - 1);
    int bh = blockIdx.x / (SS / 64);
    int hh = bh & (HH - 1);
    int b  = bh / HH;
    int q0 = qt * 64;

    const float us = u_same[hh], uc = u_cross[hh];

    {
        const float* qbase = q + ((size_t)(b * SS + q0)) * DD + hh * HD;
#pragma unroll
        for (int r = 0; r < 8; r++) {
            int idx = tid + r * 128;
            int qi  = idx >> 4;
            int c4  = (idx & 15) * 4;
            float4 a = *(const float4*)(qbase + (size_t)qi * DD + c4);
            *(uint4*)&Qs[qi * QST + c4] =
                make_uint4(f2tf(a.x), f2tf(a.y), f2tf(a.z), f2tf(a.w));
        }
    }

    int vq0 = vids[b * SS + q0 + qw + g];
    int vq1 = vids[b * SS + q0 + qw + g + 8];
    float m0 = -1e30f, m1 = -1e30f, l0 = 0.0f, l1 = 0.0f;
    float oacc[8][4];
#pragma unroll
    for (int nt = 0; nt < 8; nt++)
#pragma unroll
        for (int r = 0; r < 4; r++) oacc[nt][r] = 0.0f;
    __syncthreads();

    for (int kt = 0; kt < SS; kt += 64) {
        const float* kbase = k + ((size_t)(b * SS + kt)) * DD + hh * HD;
        const float* vbase = v + ((size_t)(b * SS + kt)) * DD + hh * HD;
#pragma unroll
        for (int r = 0; r < 8; r++) {
            int idx = tid + r * 128;
            int ki  = idx >> 4;
            int c4  = (idx & 15) * 4;
            float4 a = *(const float4*)(kbase + (size_t)ki * DD + c4);
            *(uint4*)&Ks[ki * QST + c4] =
                make_uint4(f2tf(a.x), f2tf(a.y), f2tf(a.z), f2tf(a.w));
            float4 bb = *(const float4*)(vbase + (size_t)ki * DD + c4);
            *(uint4*)&Vs[ki * VST + c4] =
                make_uint4(f2tf(bb.x), f2tf(bb.y), f2tf(bb.z), f2tf(bb.w));
        }
        if (tid < 64) {
            svid[tid]  = vids[b * SS + kt + tid];
            smask[tid] = (1.0f - mask[b * SS + kt + tid]) * -1e9f;
        }
        __syncthreads();

        float s[8][4];
#pragma unroll
        for (int nt = 0; nt < 8; nt++)
#pragma unroll
            for (int r = 0; r < 4; r++) s[nt][r] = 0.0f;
#pragma unroll
        for (int ks = 0; ks < 64; ks += 8) {
            uint32_t av[4];
            av[0] = Qs[(qw + g)     * QST + ks + tg];
            av[1] = Qs[(qw + g + 8) * QST + ks + tg];
            av[2] = Qs[(qw + g)     * QST + ks + tg + 4];
            av[3] = Qs[(qw + g + 8) * QST + ks + tg + 4];
#pragma unroll
            for (int nt = 0; nt < 8; nt++) {
                uint32_t bv[2];
                bv[0] = Ks[(nt * 8 + g) * QST + ks + tg];
                bv[1] = Ks[(nt * 8 + g) * QST + ks + tg + 4];
                mma_tf32(s[nt], av, bv);
            }
        }

        float rmax0 = -1e30f, rmax1 = -1e30f;
#pragma unroll
        for (int nt = 0; nt < 8; nt++) {
            int c0 = nt * 8 + 2 * tg;
            int c1 = c0 + 1;
            float bia0 = smask[c0], bia1 = smask[c1];
            s[nt][0] = s[nt][0] * 0.125f + (svid[c0] == vq0 ? us : uc) + bia0;
            s[nt][1] = s[nt][1] * 0.125f + (svid[c1] == vq0 ? us : uc) + bia1;
            s[nt][2] = s[nt][2] * 0.125f + (svid[c0] == vq1 ? us : uc) + bia0;
            s[nt][3] = s[nt][3] * 0.125f + (svid[c1] == vq1 ? us : uc) + bia1;
            rmax0 = fmaxf(rmax0, fmaxf(s[nt][0], s[nt][1]));
            rmax1 = fmaxf(rmax1, fmaxf(s[nt][2], s[nt][3]));
        }
        rmax0 = fmaxf(rmax0, __shfl_xor_sync(0xFFFFFFFF, rmax0, 1));
        rmax0 = fmaxf(rmax0, __shfl_xor_sync(0xFFFFFFFF, rmax0, 2));
        rmax1 = fmaxf(rmax1, __shfl_xor_sync(0xFFFFFFFF, rmax1, 1));
        rmax1 = fmaxf(rmax1, __shfl_xor_sync(0xFFFFFFFF, rmax1, 2));
        float newm0 = fmaxf(m0, rmax0);
        float newm1 = fmaxf(m1, rmax1);
        float corr0 = __expf(m0 - newm0);
        float corr1 = __expf(m1 - newm1);
        m0 = newm0; m1 = newm1;

        float rsum0 = 0.0f, rsum1 = 0.0f;
#pragma unroll
        for (int nt = 0; nt < 8; nt++) {
            float p0 = __expf(s[nt][0] - m0);
            float p1 = __expf(s[nt][1] - m0);
            float p2 = __expf(s[nt][2] - m1);
            float p3 = __expf(s[nt][3] - m1);
            rsum0 += p0 + p1;
            rsum1 += p2 + p3;
            int c0 = nt * 8 + 2 * tg;
            Ps[(qw + g)     * QST + c0]     = f2tf(p0);
            Ps[(qw + g)     * QST + c0 + 1] = f2tf(p1);
            Ps[(qw + g + 8) * QST + c0]     = f2tf(p2);
            Ps[(qw + g + 8) * QST + c0 + 1] = f2tf(p3);
            oacc[nt][0] *= corr0;
            oacc[nt][1] *= corr0;
            oacc[nt][2] *= corr1;
            oacc[nt][3] *= corr1;
        }
        rsum0 += __shfl_xor_sync(0xFFFFFFFF, rsum0, 1);
        rsum0 += __shfl_xor_sync(0xFFFFFFFF, rsum0, 2);
        rsum1 += __shfl_xor_sync(0xFFFFFFFF, rsum1, 1);
        rsum1 += __shfl_xor_sync(0xFFFFFFFF, rsum1, 2);
        l0 = l0 * corr0 + rsum0;
        l1 = l1 * corr1 + rsum1;
        __syncwarp();

#pragma unroll
        for (int ks = 0; ks < 64; ks += 8) {
            uint32_t av[4];
            av[0] = Ps[(qw + g)     * QST + ks + tg];
            av[1] = Ps[(qw + g + 8) * QST + ks + tg];
            av[2] = Ps[(qw + g)     * QST + ks + tg + 4];
            av[3] = Ps[(qw + g + 8) * QST + ks + tg + 4];
#pragma unroll
            for (int nt = 0; nt < 8; nt++) {
                uint32_t bv[2];
                bv[0] = Vs[(ks + tg)     * VST + nt * 8 + g];
                bv[1] = Vs[(ks + tg + 4) * VST + nt * 8 + g];
                mma_tf32(oacc[nt], av, bv);
            }
        }
        __syncthreads();
    }

    float invl0 = 1.0f / l0;
    float invl1 = 1.0f / l1;
    float* ob0 = o + ((size_t)(b * SS + q0 + qw + g)) * DD + hh * HD;
    float* ob1 = ob0 + (size_t)8 * DD;
#pragma unroll
    for (int nt = 0; nt < 8; nt++) {
        int c = nt * 8 + 2 * tg;
        *(float2*)(ob0 + c) = make_float2(oacc[nt][0] * invl0, oacc[nt][1] * invl0);
        *(float2*)(ob1 + c) = make_float2(oacc[nt][2] * invl1, oacc[nt][3] * invl1);
    }
}

// ---------------- driver -----------------------------------------------------
extern "C" void kernel_launch(void* const* d_in, const int* in_sizes, int n_in,
                              void* d_out, int out_size) {
    const float* x      = (const float*)d_in[0];
    const int*   vids   = (const int*)  d_in[1];
    const float* mask   = (const float*)d_in[2];
    const float* W_pe   = (const float*)d_in[3];
    const float* b_pe   = (const float*)d_in[4];
    const float* Wq     = (const float*)d_in[5];
    const float* bq     = (const float*)d_in[6];
    const float* Wk     = (const float*)d_in[7];
    const float* bk     = (const float*)d_in[8];
    const float* Wv     = (const float*)d_in[9];
    const float* bv     = (const float*)d_in[10];
    const float* Wo     = (const float*)d_in[11];
    const float* bo     = (const float*)d_in[12];
    const float* u_same = (const float*)d_in[13];
    const float* u_cross= (const float*)d_in[14];
    const float* g1     = (const float*)d_in[15];
    const float* be1    = (const float*)d_in[16];
    const float* W1     = (const float*)d_in[17];
    const float* b1f    = (const float*)d_in[18];
    const float* W2     = (const float*)d_in[19];
    const float* b2f    = (const float*)d_in[20];
    const float* g2     = (const float*)d_in[21];
    const float* be2    = (const float*)d_in[22];
    const float* Wh     = (const float*)d_in[23];
    const float* bh     = (const float*)d_in[24];
    float* out = (float*)d_out;

    float *ph, *pq, *pk, *pv, *po, *pt, *pff, *pc, *ps;
    cudaGetSymbolAddress((void**)&ph,  g_h);
    cudaGetSymbolAddress((void**)&pq,  g_q);
    cudaGetSymbolAddress((void**)&pk,  g_k);
    cudaGetSymbolAddress((void**)&pv,  g_v);
    cudaGetSymbolAddress((void**)&po,  g_o);
    cudaGetSymbolAddress((void**)&pt,  g_t);
    cudaGetSymbolAddress((void**)&pff, g_ff);
    cudaGetSymbolAddress((void**)&pc,  g_cos);
    cudaGetSymbolAddress((void**)&ps,  g_sin);

    static int smem_set = 0;
    if (!smem_set) {
        cudaFuncSetAttribute(attn3_kernel, cudaFuncAttributeMaxDynamicSharedMemorySize,
                             ATTN_SMEM_U32 * 4);
        smem_set = 1;
    }

    rope_tables_kernel<<<(SS * 32 + 255) / 256, 256>>>(pc, ps);
    tgemm_bias<0><<<dim3(DD / 128, MM / 128), 256>>>(
        x, W_pe, W_pe, W_pe, b_pe, b_pe, b_pe, ph, ph, ph, MM, DD, PP, DD / 128);

    for (int l = 0; l < LL; l++) {
        const float* Wql = Wq + (size_t)l * DD * DD;
        const float* Wkl = Wk + (size_t)l * DD * DD;
        const float* Wvl = Wv + (size_t)l * DD * DD;
        const float* Wol = Wo + (size_t)l * DD * DD;
        const float* W1l = W1 + (size_t)l * DD * DF;
        const float* W2l = W2 + (size_t)l * DF * DD;

        // fused Q,K,V projection: one grid of 3*4 x 64 blocks
        tgemm_bias<0><<<dim3(3 * (DD / 128), MM / 128), 256>>>(
            ph, Wql, Wkl, Wvl, bq + l * DD, bk + l * DD, bv + l * DD,
            pq, pk, pv, MM, DD, DD, DD / 128);

        rope_apply_kernel<<<(2 * MM * HH * 32) / 256, 256>>>(pq, pk, pc, ps);

        attn3_kernel<<<BB * HH * (SS / 64), 128, ATTN_SMEM_U32 * 4>>>(
            pq, pk, pv, vids, mask, u_same + l * HH, u_cross + l * HH, po);

        tgemm_bias<0><<<dim3(DD / 128, MM / 128), 256>>>(
            po, Wol, Wol, Wol, bo + l * DD, bo + l * DD, bo + l * DD,
            pt, pt, pt, MM, DD, DD, DD / 128);
        add_ln_kernel<<<MM, 128>>>(ph, pt, g1 + l * DD, be1 + l * DD);

        tgemm_bias<1><<<dim3(DF / 128, MM / 128), 256>>>(
            ph, W1l, W1l, W1l, b1f + l * DF, b1f + l * DF, b1f + l * DF,
            pff, pff, pff, MM, DF, DD, DF / 128);
        tgemm_bias<0><<<dim3(DD / 128, MM / 128), 256>>>(
            pff, W2l, W2l, W2l, b2f + l * DD, b2f + l * DD, b2f + l * DD,
            pt, pt, pt, MM, DD, DF, DD / 128);
        add_ln_kernel<<<MM, 128>>>(ph, pt, g2 + l * DD, be2 + l * DD);
    }

    head_gemm_kernel<<<(MM * PP) / 256, 256>>>(ph, Wh, bh, out);
}